// round 14
// baseline (speedup 1.0000x reference)
#include <cuda_runtime.h>
#include <cuda_bf16.h>
#include <cstdint>
#include <math.h>

// Problem constants (fixed by reference setup)
#define TQS 2048
#define TKS 2048
#define DDIM 2048
#define IDIM 2048
#define NHEAD 16
#define HDIM 128
#define NBATCH 2
#define NBH (NBATCH*NHEAD)

typedef __nv_bfloat16 bf16;

// ---------------- scratch (device globals; no runtime allocation) -----------
__device__ bf16  g_Xq [(size_t)NBATCH*TQS*DDIM];
__device__ bf16  g_Xkv[(size_t)NBATCH*TKS*DDIM];
__device__ bf16  g_Wq [(size_t)IDIM*DDIM];
__device__ bf16  g_Wk [(size_t)IDIM*DDIM];
__device__ bf16  g_Wv [(size_t)IDIM*DDIM];
__device__ bf16  g_Wo [(size_t)DDIM*IDIM];
__device__ bf16  g_Q  [(size_t)NBATCH*TQS*IDIM];
__device__ bf16  g_K  [(size_t)NBATCH*TKS*IDIM];
__device__ bf16  g_V  [(size_t)NBATCH*TKS*IDIM];
__device__ bf16  g_Ctx[(size_t)NBATCH*TQS*IDIM];
__device__ int   g_maskByte;

// ---------------- helpers -----------------------------------------------------
__device__ __forceinline__ uint32_t s2u(const void* p) {
    return (uint32_t)__cvta_generic_to_shared(p);
}
__device__ __forceinline__ void cpa16(void* dst, const void* src) {
    uint32_t d = s2u(dst);
    asm volatile("cp.async.cg.shared.global [%0], [%1], 16;\n" :: "r"(d), "l"(src));
}
#define CP_COMMIT() asm volatile("cp.async.commit_group;\n" ::: "memory")
#define CP_WAIT(N)  asm volatile("cp.async.wait_group %0;\n" :: "n"(N) : "memory")

// single-instruction exp2 (MUFU.EX2); input <= 0 or -inf in our uses
__device__ __forceinline__ float ex2(float x) {
    float y;
    asm("ex2.approx.ftz.f32 %0, %1;" : "=f"(y) : "f"(x));
    return y;
}

__device__ __forceinline__ void mma16816(float c[4], const uint32_t a[4], const uint32_t b[2]) {
    asm volatile(
        "mma.sync.aligned.m16n8k16.row.col.f32.bf16.bf16.f32 "
        "{%0,%1,%2,%3}, {%4,%5,%6,%7}, {%8,%9}, {%0,%1,%2,%3};\n"
        : "+f"(c[0]), "+f"(c[1]), "+f"(c[2]), "+f"(c[3])
        : "r"(a[0]), "r"(a[1]), "r"(a[2]), "r"(a[3]), "r"(b[0]), "r"(b[1]));
}
__device__ __forceinline__ void ldsm_x4(uint32_t r[4], uint32_t addr) {
    asm volatile("ldmatrix.sync.aligned.m8n8.x4.shared.b16 {%0,%1,%2,%3}, [%4];"
        : "=r"(r[0]), "=r"(r[1]), "=r"(r[2]), "=r"(r[3]) : "r"(addr));
}
__device__ __forceinline__ void ldsm_x4_t(uint32_t r[4], uint32_t addr) {
    asm volatile("ldmatrix.sync.aligned.m8n8.x4.trans.shared.b16 {%0,%1,%2,%3}, [%4];"
        : "=r"(r[0]), "=r"(r[1]), "=r"(r[2]), "=r"(r[3]) : "r"(addr));
}

// ---------------- GEMM core: C(128x256) += A(128xK) * B(256xK)^T ------------
// 8 warps (2m x 4n), warp tile 64x64. 4-stage cp.async, one barrier / 2 K-steps.
#define BM 128
#define BN 256
#define BK 32
#define SAST 40   // padded smem stride (bf16); LDSM conflict-free
#define FST 136   // padded smem stride for flash tiles
#define GSTAGE ((BM + BN) * SAST)                    // bf16 elems per stage (A+B)
#define GEMM_SMEM (4 * GSTAGE * (int)sizeof(bf16))   // 122880 B

__device__ __forceinline__ void gemm_mma_step(
    const bf16* __restrict__ SA, const bf16* __restrict__ SB,
    int wm, int wn, int aRow, int aCol, int bRow, int bCol,
    float (&acc)[4][8][4])
{
#pragma unroll
    for (int kk = 0; kk < BK; kk += 16) {
        uint32_t af[4][4];
#pragma unroll
        for (int mi = 0; mi < 4; mi++) {
            int row = wm * 64 + mi * 16 + aRow;
            ldsm_x4(af[mi], s2u(SA + row * SAST + kk + aCol));
        }
        uint32_t bq[4][4];
#pragma unroll
        for (int p = 0; p < 4; p++) {
            int n = wn * 64 + p * 16 + bRow;
            ldsm_x4(bq[p], s2u(SB + n * SAST + kk + bCol));
        }
#pragma unroll
        for (int mi = 0; mi < 4; mi++)
#pragma unroll
            for (int ni = 0; ni < 8; ni++)
                mma16816(acc[mi][ni], af[mi], &bq[ni >> 1][(ni & 1) * 2]);
    }
}

__device__ __forceinline__ void gemm_core4(
    const bf16* __restrict__ A, int lda,
    const bf16* __restrict__ Bm, int ldb,
    int nSteps, float (&acc)[4][8][4], bf16* __restrict__ smem)
{
    const int t    = threadIdx.x;
    const int lane = t & 31;
    const int warp = t >> 5;
    const int wm   = warp & 1;
    const int wn   = warp >> 1;

    const int aRow = (lane & 15);
    const int aCol = ((lane >> 4) << 3);
    const int bRow = (lane & 7) + ((lane >> 4) << 3);
    const int bCol = (((lane >> 3) & 1) << 3);

    auto loadStage = [&](int k0, int st) {
        bf16* SA = smem + st * GSTAGE;
        bf16* SB = SA + BM * SAST;
        // A: 128 rows x 4 chunks = 512; B: 256 rows x 4 chunks = 1024
#pragma unroll
        for (int i = 0; i < 2; i++) {
            int idx = t + i * 256;
            int r = idx >> 2;
            int c = (idx & 3) << 3;
            cpa16(&SA[r * SAST + c], A + (size_t)r * lda + k0 + c);
        }
#pragma unroll
        for (int i = 0; i < 4; i++) {
            int idx = t + i * 256;
            int r = idx >> 2;
            int c = (idx & 3) << 3;
            cpa16(&SB[r * SAST + c], Bm + (size_t)r * ldb + k0 + c);
        }
        CP_COMMIT();
    };

    loadStage(0, 0);
    loadStage(BK, 1);

    // nSteps is even
    for (int s = 0; s < nSteps; s += 2) {
        CP_WAIT(0);
        __syncthreads();
        if (s + 2 < nSteps) loadStage((s + 2) * BK, (s + 2) & 3);
        if (s + 3 < nSteps) loadStage((s + 3) * BK, (s + 3) & 3);

        const bf16* SA0 = smem + (s & 3) * GSTAGE;
        gemm_mma_step(SA0, SA0 + BM * SAST, wm, wn, aRow, aCol, bRow, bCol, acc);
        const bf16* SA1 = smem + ((s + 1) & 3) * GSTAGE;
        gemm_mma_step(SA1, SA1 + BM * SAST, wm, wn, aRow, aCol, bRow, bCol, acc);
    }
}

#define GEMM_PROLOG()                              \
    float acc[4][8][4];                            \
    _Pragma("unroll") for (int a_=0;a_<4;a_++)     \
    _Pragma("unroll") for (int b_=0;b_<8;b_++)     \
    _Pragma("unroll") for (int c_=0;c_<4;c_++) acc[a_][b_][c_] = 0.f;

#define EPI_VARS()                                  \
    const int lane = threadIdx.x & 31;              \
    const int warp = threadIdx.x >> 5;              \
    const int wm = warp & 1, wn = warp >> 1;        \
    const int grp = lane >> 2, tid4 = lane & 3;

// ---------------- fused Q/K/V projection (blockIdx.z selects matrix) ---------
struct QkvArgs {
    const bf16* X[3];
    const bf16* W[3];
    const float* bias[3];
    bf16* out[3];
};
__global__ __launch_bounds__(256, 1) void k_qkv(QkvArgs a)
{
    extern __shared__ bf16 dsm[];
    const int z = blockIdx.z;
    const int m0 = blockIdx.y * BM;
    const int n0 = blockIdx.x * BN;
    const bf16* X = a.X[z];
    const bf16* W = a.W[z];
    const float* bias = a.bias[z];
    bf16* Cout = a.out[z];

    GEMM_PROLOG();
    gemm_core4(X + (size_t)m0 * DDIM, DDIM, W + (size_t)n0 * DDIM, DDIM,
               DDIM / BK, acc, dsm);
    EPI_VARS();
#pragma unroll
    for (int mi = 0; mi < 4; mi++)
#pragma unroll
        for (int ni = 0; ni < 8; ni++)
#pragma unroll
            for (int hh = 0; hh < 2; hh++) {
                int r = m0 + wm * 64 + mi * 16 + grp + hh * 8;
                int c = n0 + wn * 64 + ni * 8 + tid4 * 2;
                float v0 = acc[mi][ni][hh * 2 + 0] + bias[c];
                float v1 = acc[mi][ni][hh * 2 + 1] + bias[c + 1];
                __nv_bfloat162 o;
                o.x = __float2bfloat16(v0);
                o.y = __float2bfloat16(v1);
                *(__nv_bfloat162*)&Cout[(size_t)r * IDIM + c] = o;
            }
}

// out = query + (ctx * Wo^T + bo) * sigmoid(gate)
__global__ __launch_bounds__(256, 1) void k_out(
    const float* __restrict__ query, const float* __restrict__ bo,
    const float* __restrict__ gate, float* __restrict__ out)
{
    extern __shared__ bf16 dsm[];
    const int m0 = blockIdx.y * BM;
    const int n0 = blockIdx.x * BN;
    const float L2E = 1.4426950408889634f;
    GEMM_PROLOG();
    gemm_core4(g_Ctx + (size_t)m0 * IDIM, IDIM, g_Wo + (size_t)n0 * IDIM, IDIM,
               IDIM / BK, acc, dsm);
    EPI_VARS();
#pragma unroll
    for (int mi = 0; mi < 4; mi++)
#pragma unroll
        for (int ni = 0; ni < 8; ni++)
#pragma unroll
            for (int hh = 0; hh < 2; hh++) {
                int r = m0 + wm * 64 + mi * 16 + grp + hh * 8;
                int c = n0 + wn * 64 + ni * 8 + tid4 * 2;
                float g0 = 1.f / (1.f + ex2(-gate[c]     * L2E));
                float g1 = 1.f / (1.f + ex2(-gate[c + 1] * L2E));
                float v0 = (acc[mi][ni][hh * 2 + 0] + bo[c])     * g0;
                float v1 = (acc[mi][ni][hh * 2 + 1] + bo[c + 1]) * g1;
                float2 qv = *(const float2*)&query[(size_t)r * DDIM + c];
                float2 o; o.x = qv.x + v0; o.y = qv.y + v1;
                *(float2*)&out[(size_t)r * DDIM + c] = o;
            }
}

// ---------------- fused flash attention (2-stage pipelined, ldmatrix) --------
// Largest-first scheduling; exp2-domain softmax (MUFU.EX2); masked-tile fast path.
__global__ __launch_bounds__(256) void k_flash(const unsigned char* __restrict__ maskRaw)
{
    const int qt = (int)gridDim.x - 1 - (int)blockIdx.x;   // big CTAs first
    const int bh = blockIdx.y;
    const int b = bh >> 4, h = bh & 15;

    extern __shared__ bf16 sm[];
    __shared__ unsigned char mk[2][128];

    const int t = threadIdx.x, lane = t & 31, w = t >> 5;
    const int grp = lane >> 2, tid4 = lane & 3;
    const int useByte = g_maskByte;

    const int kRow = (lane & 7) + ((lane >> 4) << 3);
    const int kCol = (((lane >> 3) & 1) << 3);
    const int vRow = (lane & 15);
    const int vCol = ((lane >> 4) << 3);

    // scores scaled by C = 1/sqrt(128) * log2(e); all exponentials are exp2.
    const float C = 0.088388347648318447f * 1.4426950408889634f;

    // --- stage Q tile through stage-0 area, extract persistent A-fragments ---
    {
        bf16* SQ = sm;
        const bf16* Qg = g_Q + ((size_t)(b * TQS + qt * 128)) * IDIM + h * HDIM;
#pragma unroll
        for (int i = 0; i < 8; i++) {
            int idx = t + i * 256;
            int r = idx >> 4;
            int c = (idx & 15) * 8;
            *(float4*)(SQ + r * FST + c) = *(const float4*)(Qg + (size_t)r * IDIM + c);
        }
    }
    __syncthreads();
    uint32_t qf[8][4];
    {
        const bf16* SQ = sm;
        const int row = w * 16 + (lane & 15);
#pragma unroll
        for (int kc = 0; kc < 8; kc++)
            ldsm_x4(qf[kc], s2u(SQ + row * FST + kc * 16 + ((lane >> 4) << 3)));
    }
    __syncthreads();

    const bf16* Kb = g_K + ((size_t)(b * TKS)) * IDIM + h * HDIM;
    const bf16* Vb = g_V + ((size_t)(b * TKS)) * IDIM + h * HDIM;

    auto prefetch = [&](int kt, int s) {
        bf16* SK = sm + (size_t)s * (2 * 128 * FST);
        bf16* SV = SK + 128 * FST;
        const bf16* Kg = Kb + (size_t)(kt * 128) * IDIM;
        const bf16* Vg = Vb + (size_t)(kt * 128) * IDIM;
#pragma unroll
        for (int i = 0; i < 8; i++) {
            int idx = t + i * 256;
            int r = idx >> 4;
            int c = (idx & 15) * 8;
            cpa16(&SK[r * FST + c], Kg + (size_t)r * IDIM + c);
            cpa16(&SV[r * FST + c], Vg + (size_t)r * IDIM + c);
        }
        if (t < 128) {
            int k = kt * 128 + t;
            int mv = useByte ? (int)maskRaw[(size_t)b * TKS + k]
                             : ((const int*)maskRaw)[(size_t)b * TKS + k];
            mk[s][t] = (unsigned char)(mv != 0);
        }
        CP_COMMIT();
    };

    float m0 = -INFINITY, m1 = -INFINITY, l0 = 0.f, l1 = 0.f;
    float ao[16][4];
#pragma unroll
    for (int ni = 0; ni < 16; ni++)
#pragma unroll
        for (int j = 0; j < 4; j++) ao[ni][j] = 0.f;

    const int q0 = qt * 128 + w * 16 + grp;
    const int q1 = q0 + 8;

    prefetch(0, 0);
    int buf = 0;

    for (int kt = 0; kt <= qt; kt++) {
        if (kt < qt) {
            prefetch(kt + 1, buf ^ 1);
            CP_WAIT(1);
        } else {
            CP_WAIT(0);
        }
        __syncthreads();

        const bf16* SK = sm + (size_t)buf * (2 * 128 * FST);
        const bf16* SV = SK + 128 * FST;

        // --- S = Q K^T (16x128 per warp) ---
        float as_[16][4];
#pragma unroll
        for (int ni = 0; ni < 16; ni++)
#pragma unroll
            for (int j = 0; j < 4; j++) as_[ni][j] = 0.f;
#pragma unroll
        for (int kc = 0; kc < 8; kc++) {
#pragma unroll
            for (int ni = 0; ni < 16; ni += 2) {
                uint32_t bq[4];
                int n = ni * 8 + kRow;
                ldsm_x4(bq, s2u(SK + n * FST + kc * 16 + kCol));
                mma16816(as_[ni],     qf[kc], bq);
                mma16816(as_[ni + 1], qf[kc], bq + 2);
            }
        }

        // --- tile classification: clean (no causal, no padding) vs heavy ---
        bool heavy = (kt == qt);
        {
            uint32_t m4 = ((const uint32_t*)mk[buf])[lane];
            if (__ballot_sync(0xffffffffu, m4 != 0)) heavy = true;
        }

        // --- scale (+ masks on heavy path); row max (exp2 domain) ---
        float tm0 = -INFINITY, tm1 = -INFINITY;
        if (!heavy) {
#pragma unroll
            for (int ni = 0; ni < 16; ni++) {
                float s0 = as_[ni][0] * C;
                float s1 = as_[ni][1] * C;
                float s2 = as_[ni][2] * C;
                float s3 = as_[ni][3] * C;
                as_[ni][0] = s0; as_[ni][1] = s1; as_[ni][2] = s2; as_[ni][3] = s3;
                tm0 = fmaxf(tm0, fmaxf(s0, s1));
                tm1 = fmaxf(tm1, fmaxf(s2, s3));
            }
        } else {
#pragma unroll
            for (int ni = 0; ni < 16; ni++) {
                int kc0 = ni * 8 + tid4 * 2;
                int kg = kt * 128 + kc0;
                bool pm0 = mk[buf][kc0] != 0, pm1 = mk[buf][kc0 + 1] != 0;
                float s0 = (kg     > q0 || pm0) ? -INFINITY : as_[ni][0] * C;
                float s1 = (kg + 1 > q0 || pm1) ? -INFINITY : as_[ni][1] * C;
                float s2 = (kg     > q1 || pm0) ? -INFINITY : as_[ni][2] * C;
                float s3 = (kg + 1 > q1 || pm1) ? -INFINITY : as_[ni][3] * C;
                as_[ni][0] = s0; as_[ni][1] = s1; as_[ni][2] = s2; as_[ni][3] = s3;
                tm0 = fmaxf(tm0, fmaxf(s0, s1));
                tm1 = fmaxf(tm1, fmaxf(s2, s3));
            }
        }
        tm0 = fmaxf(tm0, __shfl_xor_sync(0xffffffffu, tm0, 1));
        tm0 = fmaxf(tm0, __shfl_xor_sync(0xffffffffu, tm0, 2));
        tm1 = fmaxf(tm1, __shfl_xor_sync(0xffffffffu, tm1, 1));
        tm1 = fmaxf(tm1, __shfl_xor_sync(0xffffffffu, tm1, 2));

        // --- online softmax update (exp2 domain, MUFU.EX2) ---
        float mn0 = fmaxf(m0, tm0), mn1 = fmaxf(m1, tm1);
        float f0 = ex2(m0 - mn0), f1 = ex2(m1 - mn1);
        m0 = mn0; m1 = mn1;

        float rs0 = 0.f, rs1 = 0.f;
#pragma unroll
        for (int ni = 0; ni < 16; ni++) {
            float p0 = ex2(as_[ni][0] - mn0);
            float p1 = ex2(as_[ni][1] - mn0);
            float p2 = ex2(as_[ni][2] - mn1);
            float p3 = ex2(as_[ni][3] - mn1);
            as_[ni][0] = p0; as_[ni][1] = p1; as_[ni][2] = p2; as_[ni][3] = p3;
            rs0 += p0 + p1;
            rs1 += p2 + p3;
        }
        rs0 += __shfl_xor_sync(0xffffffffu, rs0, 1);
        rs0 += __shfl_xor_sync(0xffffffffu, rs0, 2);
        rs1 += __shfl_xor_sync(0xffffffffu, rs1, 1);
        rs1 += __shfl_xor_sync(0xffffffffu, rs1, 2);
        l0 = l0 * f0 + rs0;
        l1 = l1 * f1 + rs1;

        // --- rescale O accumulator ---
#pragma unroll
        for (int ni = 0; ni < 16; ni++) {
            ao[ni][0] *= f0; ao[ni][1] *= f0;
            ao[ni][2] *= f1; ao[ni][3] *= f1;
        }

        // --- O += P V (P in regs; V via ldmatrix.trans) ---
#pragma unroll
        for (int kc = 0; kc < 8; kc++) {
            uint32_t pf[4];
            __nv_bfloat162 h0 = __float22bfloat162_rn(make_float2(as_[2*kc][0],   as_[2*kc][1]));
            __nv_bfloat162 h1 = __float22bfloat162_rn(make_float2(as_[2*kc][2],   as_[2*kc][3]));
            __nv_bfloat162 h2 = __float22bfloat162_rn(make_float2(as_[2*kc+1][0], as_[2*kc+1][1]));
            __nv_bfloat162 h3 = __float22bfloat162_rn(make_float2(as_[2*kc+1][2], as_[2*kc+1][3]));
            pf[0] = *(uint32_t*)&h0;
            pf[1] = *(uint32_t*)&h1;
            pf[2] = *(uint32_t*)&h2;
            pf[3] = *(uint32_t*)&h3;
#pragma unroll
            for (int ni = 0; ni < 16; ni += 2) {
                uint32_t bq[4];
                int row = kc * 16 + vRow;
                ldsm_x4_t(bq, s2u(SV + row * FST + ni * 8 + vCol));
                mma16816(ao[ni],     pf, bq);
                mma16816(ao[ni + 1], pf, bq + 2);
            }
        }
        __syncthreads();
        buf ^= 1;
    }

    // --- normalize and write ctx (bf16) ---
    const float inv0 = 1.f / l0, inv1 = 1.f / l1;
    bf16* Cg = g_Ctx + ((size_t)(b * TQS + qt * 128 + w * 16)) * IDIM + h * HDIM;
#pragma unroll
    for (int ni = 0; ni < 16; ni++) {
        int c = ni * 8 + tid4 * 2;
        __nv_bfloat162 o0 = __float22bfloat162_rn(make_float2(ao[ni][0] * inv0, ao[ni][1] * inv0));
        __nv_bfloat162 o1 = __float22bfloat162_rn(make_float2(ao[ni][2] * inv1, ao[ni][3] * inv1));
        *(__nv_bfloat162*)(Cg + (size_t)grp * IDIM + c)       = o0;
        *(__nv_bfloat162*)(Cg + (size_t)(grp + 8) * IDIM + c) = o1;
    }
}

// fused fp32 -> bf16 conversion over all 6 arrays in one launch
struct CvtArgs {
    const float* src[6];
    bf16* dst[6];
    int end[6];   // cumulative block ends
};
__global__ __launch_bounds__(256) void k_cvt_all(CvtArgs a)
{
    int blk = blockIdx.x;
    int seg = 0;
#pragma unroll
    for (int s = 0; s < 5; s++) seg += (blk >= a.end[s]) ? 1 : 0;
    int base = seg ? a.end[seg - 1] : 0;
    int i = (((blk - base) * 256) + threadIdx.x) * 4;
    float4 v = *(const float4*)(a.src[seg] + i);
    __nv_bfloat162 x, y;
    x.x = __float2bfloat16(v.x); x.y = __float2bfloat16(v.y);
    y.x = __float2bfloat16(v.z); y.y = __float2bfloat16(v.w);
    *(__nv_bfloat162*)(a.dst[seg] + i)     = x;
    *(__nv_bfloat162*)(a.dst[seg] + i + 2) = y;
}

// detect mask storage layout: byte 4095 == 1 => 1-byte bool; == 0 => int32
__global__ void k_detect(const unsigned char* __restrict__ mask)
{
    g_maskByte = (mask[(size_t)NBATCH * TKS - 1] != 0) ? 1 : 0;
}

// ---------------- launch -----------------------------------------------------
extern "C" void kernel_launch(void* const* d_in, const int* in_sizes, int n_in,
                              void* d_out, int out_size)
{
    const float* query = (const float*)d_in[0];
    const float* kv    = (const float*)d_in[1];
    const unsigned char* mask = (const unsigned char*)d_in[2];
    const float* Wq = (const float*)d_in[3];
    const float* bq = (const float*)d_in[4];
    const float* Wk = (const float*)d_in[5];
    const float* bk = (const float*)d_in[6];
    const float* Wv = (const float*)d_in[7];
    const float* bv = (const float*)d_in[8];
    const float* Wo = (const float*)d_in[9];
    const float* bo = (const float*)d_in[10];
    const float* gate = (const float*)d_in[11];
    float* out = (float*)d_out;

    // symbol addresses
    bf16 *pXq, *pXkv, *pWq, *pWk, *pWv, *pWo, *pQ, *pK, *pV;
    cudaGetSymbolAddress((void**)&pXq,  g_Xq);
    cudaGetSymbolAddress((void**)&pXkv, g_Xkv);
    cudaGetSymbolAddress((void**)&pWq,  g_Wq);
    cudaGetSymbolAddress((void**)&pWk,  g_Wk);
    cudaGetSymbolAddress((void**)&pWv,  g_Wv);
    cudaGetSymbolAddress((void**)&pWo,  g_Wo);
    cudaGetSymbolAddress((void**)&pQ,   g_Q);
    cudaGetSymbolAddress((void**)&pK,   g_K);
    cudaGetSymbolAddress((void**)&pV,   g_V);

    static int attrSet = 0;
    const int FLASH_SMEM = 2 * 2 * 128 * FST * (int)sizeof(bf16);  // 139264
    if (!attrSet) {
        cudaFuncSetAttribute(k_flash, cudaFuncAttributeMaxDynamicSharedMemorySize, FLASH_SMEM);
        cudaFuncSetAttribute(k_qkv,   cudaFuncAttributeMaxDynamicSharedMemorySize, GEMM_SMEM);
        cudaFuncSetAttribute(k_out,   cudaFuncAttributeMaxDynamicSharedMemorySize, GEMM_SMEM);
        attrSet = 1;
    }

    k_detect<<<1, 1>>>(mask);

    // fused conversions: tokens (2 x 8.4M) + weights (4 x 4.2M)
    {
        CvtArgs a;
        a.src[0] = query; a.dst[0] = pXq;
        a.src[1] = kv;    a.dst[1] = pXkv;
        a.src[2] = Wq;    a.dst[2] = pWq;
        a.src[3] = Wk;    a.dst[3] = pWk;
        a.src[4] = Wv;    a.dst[4] = pWv;
        a.src[5] = Wo;    a.dst[5] = pWo;
        const int nTokB = NBATCH * TQS * DDIM / 1024;  // 8192 blocks
        const int nWB   = IDIM * DDIM / 1024;          // 4096 blocks
        int e = 0;
        e += nTokB; a.end[0] = e;
        e += nTokB; a.end[1] = e;
        e += nWB;   a.end[2] = e;
        e += nWB;   a.end[3] = e;
        e += nWB;   a.end[4] = e;
        e += nWB;   a.end[5] = e;
        k_cvt_all<<<e, 256>>>(a);
    }

    // fused Q/K/V projections: one launch, z in {0,1,2}
    {
        QkvArgs qa;
        qa.X[0] = pXq;  qa.W[0] = pWq; qa.bias[0] = bq; qa.out[0] = pQ;
        qa.X[1] = pXkv; qa.W[1] = pWk; qa.bias[1] = bk; qa.out[1] = pK;
        qa.X[2] = pXkv; qa.W[2] = pWv; qa.bias[2] = bv; qa.out[2] = pV;
        dim3 g(IDIM / BN, NBATCH * TQS / BM, 3);       // (8, 32, 3)
        k_qkv<<<g, 256, GEMM_SMEM>>>(qa);
    }

    k_flash<<<dim3(TQS / 128, NBH), 256, FLASH_SMEM>>>(mask);

    k_out<<<dim3(DDIM / BN, NBATCH * TQS / BM), 256, GEMM_SMEM>>>(query, bo, gate, out);
}

// round 15
// speedup vs baseline: 1.0878x; 1.0878x over previous
#include <cuda_runtime.h>
#include <cuda_bf16.h>
#include <cstdint>
#include <math.h>

// Problem constants (fixed by reference setup)
#define TQS 2048
#define TKS 2048
#define DDIM 2048
#define IDIM 2048
#define NHEAD 16
#define HDIM 128
#define NBATCH 2
#define NBH (NBATCH*NHEAD)

typedef __nv_bfloat16 bf16;

// ---------------- scratch (device globals; no runtime allocation) -----------
__device__ bf16  g_Xq [(size_t)NBATCH*TQS*DDIM];
__device__ bf16  g_Xkv[(size_t)NBATCH*TKS*DDIM];
__device__ bf16  g_Wq [(size_t)IDIM*DDIM];
__device__ bf16  g_Wk [(size_t)IDIM*DDIM];
__device__ bf16  g_Wv [(size_t)IDIM*DDIM];
__device__ bf16  g_Wo [(size_t)DDIM*IDIM];
__device__ bf16  g_Q  [(size_t)NBATCH*TQS*IDIM];
__device__ bf16  g_K  [(size_t)NBATCH*TKS*IDIM];
__device__ bf16  g_V  [(size_t)NBATCH*TKS*IDIM];
__device__ bf16  g_Ctx[(size_t)NBATCH*TQS*IDIM];
__device__ int   g_maskByte;

// ---------------- helpers -----------------------------------------------------
__device__ __forceinline__ uint32_t s2u(const void* p) {
    return (uint32_t)__cvta_generic_to_shared(p);
}
__device__ __forceinline__ void cpa16(void* dst, const void* src) {
    uint32_t d = s2u(dst);
    asm volatile("cp.async.cg.shared.global [%0], [%1], 16;\n" :: "r"(d), "l"(src));
}
#define CP_COMMIT() asm volatile("cp.async.commit_group;\n" ::: "memory")
#define CP_WAIT(N)  asm volatile("cp.async.wait_group %0;\n" :: "n"(N) : "memory")

// single-instruction exp2 (MUFU.EX2); input <= 0 or -inf in our uses
__device__ __forceinline__ float ex2(float x) {
    float y;
    asm("ex2.approx.ftz.f32 %0, %1;" : "=f"(y) : "f"(x));
    return y;
}

__device__ __forceinline__ void mma16816(float c[4], const uint32_t a[4], const uint32_t b[2]) {
    asm volatile(
        "mma.sync.aligned.m16n8k16.row.col.f32.bf16.bf16.f32 "
        "{%0,%1,%2,%3}, {%4,%5,%6,%7}, {%8,%9}, {%0,%1,%2,%3};\n"
        : "+f"(c[0]), "+f"(c[1]), "+f"(c[2]), "+f"(c[3])
        : "r"(a[0]), "r"(a[1]), "r"(a[2]), "r"(a[3]), "r"(b[0]), "r"(b[1]));
}
__device__ __forceinline__ void ldsm_x4(uint32_t r[4], uint32_t addr) {
    asm volatile("ldmatrix.sync.aligned.m8n8.x4.shared.b16 {%0,%1,%2,%3}, [%4];"
        : "=r"(r[0]), "=r"(r[1]), "=r"(r[2]), "=r"(r[3]) : "r"(addr));
}
__device__ __forceinline__ void ldsm_x4_t(uint32_t r[4], uint32_t addr) {
    asm volatile("ldmatrix.sync.aligned.m8n8.x4.trans.shared.b16 {%0,%1,%2,%3}, [%4];"
        : "=r"(r[0]), "=r"(r[1]), "=r"(r[2]), "=r"(r[3]) : "r"(addr));
}

// ---------------- GEMM core: C(128x128) += A(128xK) * B(128xK)^T ------------
// 4-stage cp.async pipeline, ONE __syncthreads per TWO K-steps. 2 CTAs/SM.
#define BM 128
#define BN 128
#define BK 32
#define SAST 40   // padded smem stride (bf16); LDSM conflict-free
#define FST 136   // padded smem stride for flash tiles
#define GSTAGE (2 * 128 * SAST)                      // bf16 elems per stage (A+B)
#define GEMM_SMEM (4 * GSTAGE * (int)sizeof(bf16))   // 81920 B

__device__ __forceinline__ void gemm_mma_step(
    const bf16* __restrict__ SA, const bf16* __restrict__ SB,
    int wm, int wn, int aRow, int aCol, int bRow, int bCol,
    float (&acc)[4][4][4])
{
#pragma unroll
    for (int kk = 0; kk < BK; kk += 16) {
        uint32_t af[4][4];
#pragma unroll
        for (int mi = 0; mi < 4; mi++) {
            int row = wm * 64 + mi * 16 + aRow;
            ldsm_x4(af[mi], s2u(SA + row * SAST + kk + aCol));
        }
        uint32_t bq[2][4];
#pragma unroll
        for (int p = 0; p < 2; p++) {
            int n = wn * 32 + p * 16 + bRow;
            ldsm_x4(bq[p], s2u(SB + n * SAST + kk + bCol));
        }
#pragma unroll
        for (int mi = 0; mi < 4; mi++)
#pragma unroll
            for (int ni = 0; ni < 4; ni++)
                mma16816(acc[mi][ni], af[mi], &bq[ni >> 1][(ni & 1) * 2]);
    }
}

__device__ __forceinline__ void gemm_core4(
    const bf16* __restrict__ A, int lda,
    const bf16* __restrict__ Bm, int ldb,
    int nSteps, float (&acc)[4][4][4], bf16* __restrict__ smem)
{
    const int t    = threadIdx.x;
    const int lane = t & 31;
    const int warp = t >> 5;
    const int wm   = warp & 1;
    const int wn   = warp >> 1;

    const int aRow = (lane & 15);
    const int aCol = ((lane >> 4) << 3);
    const int bRow = (lane & 7) + ((lane >> 4) << 3);
    const int bCol = (((lane >> 3) & 1) << 3);

    auto loadStage = [&](int k0, int st) {
        bf16* SA = smem + st * GSTAGE;
        bf16* SB = SA + 128 * SAST;
#pragma unroll
        for (int i = 0; i < 2; i++) {
            int idx = t + i * 256;
            int r = idx >> 2;
            int c = (idx & 3) << 3;
            cpa16(&SA[r * SAST + c], A  + (size_t)r * lda + k0 + c);
            cpa16(&SB[r * SAST + c], Bm + (size_t)r * ldb + k0 + c);
        }
        CP_COMMIT();
    };

    loadStage(0, 0);
    loadStage(BK, 1);

    // nSteps is even (K multiples of 64)
    for (int s = 0; s < nSteps; s += 2) {
        CP_WAIT(0);
        __syncthreads();
        if (s + 2 < nSteps) loadStage((s + 2) * BK, (s + 2) & 3);
        if (s + 3 < nSteps) loadStage((s + 3) * BK, (s + 3) & 3);

        const bf16* SA0 = smem + (s & 3) * GSTAGE;
        gemm_mma_step(SA0, SA0 + 128 * SAST, wm, wn, aRow, aCol, bRow, bCol, acc);
        const bf16* SA1 = smem + ((s + 1) & 3) * GSTAGE;
        gemm_mma_step(SA1, SA1 + 128 * SAST, wm, wn, aRow, aCol, bRow, bCol, acc);
    }
}

#define GEMM_PROLOG()                              \
    float acc[4][4][4];                            \
    _Pragma("unroll") for (int a_=0;a_<4;a_++)     \
    _Pragma("unroll") for (int b_=0;b_<4;b_++)     \
    _Pragma("unroll") for (int c_=0;c_<4;c_++) acc[a_][b_][c_] = 0.f;

#define EPI_VARS()                                  \
    const int lane = threadIdx.x & 31;              \
    const int warp = threadIdx.x >> 5;              \
    const int wm = warp & 1, wn = warp >> 1;        \
    const int grp = lane >> 2, tid4 = lane & 3;

// ---------------- fused Q/K/V projection (blockIdx.z selects matrix) ---------
struct QkvArgs {
    const bf16* X[3];
    const bf16* W[3];
    const float* bias[3];
    bf16* out[3];
};
__global__ __launch_bounds__(256, 2) void k_qkv(QkvArgs a)
{
    extern __shared__ bf16 dsm[];
    const int z = blockIdx.z;
    const int m0 = blockIdx.y * BM;
    const int n0 = blockIdx.x * BN;
    const bf16* X = a.X[z];
    const bf16* W = a.W[z];
    const float* bias = a.bias[z];
    bf16* Cout = a.out[z];

    GEMM_PROLOG();
    gemm_core4(X + (size_t)m0 * DDIM, DDIM, W + (size_t)n0 * DDIM, DDIM,
               DDIM / BK, acc, dsm);
    EPI_VARS();
#pragma unroll
    for (int mi = 0; mi < 4; mi++)
#pragma unroll
        for (int ni = 0; ni < 4; ni++)
#pragma unroll
            for (int hh = 0; hh < 2; hh++) {
                int r = m0 + wm * 64 + mi * 16 + grp + hh * 8;
                int c = n0 + wn * 32 + ni * 8 + tid4 * 2;
                float v0 = acc[mi][ni][hh * 2 + 0] + bias[c];
                float v1 = acc[mi][ni][hh * 2 + 1] + bias[c + 1];
                __nv_bfloat162 o;
                o.x = __float2bfloat16(v0);
                o.y = __float2bfloat16(v1);
                *(__nv_bfloat162*)&Cout[(size_t)r * IDIM + c] = o;
            }
}

// out = query + (ctx * Wo^T + bo) * sigmoid(gate)
__global__ __launch_bounds__(256, 2) void k_out(
    const float* __restrict__ query, const float* __restrict__ bo,
    const float* __restrict__ gate, float* __restrict__ out)
{
    extern __shared__ bf16 dsm[];
    const int m0 = blockIdx.y * BM;
    const int n0 = blockIdx.x * BN;
    const float L2E = 1.4426950408889634f;
    GEMM_PROLOG();
    gemm_core4(g_Ctx + (size_t)m0 * IDIM, IDIM, g_Wo + (size_t)n0 * IDIM, IDIM,
               IDIM / BK, acc, dsm);
    EPI_VARS();
#pragma unroll
    for (int mi = 0; mi < 4; mi++)
#pragma unroll
        for (int ni = 0; ni < 4; ni++)
#pragma unroll
            for (int hh = 0; hh < 2; hh++) {
                int r = m0 + wm * 64 + mi * 16 + grp + hh * 8;
                int c = n0 + wn * 32 + ni * 8 + tid4 * 2;
                float g0 = 1.f / (1.f + ex2(-gate[c]     * L2E));
                float g1 = 1.f / (1.f + ex2(-gate[c + 1] * L2E));
                float v0 = (acc[mi][ni][hh * 2 + 0] + bo[c])     * g0;
                float v1 = (acc[mi][ni][hh * 2 + 1] + bo[c + 1]) * g1;
                float2 qv = *(const float2*)&query[(size_t)r * DDIM + c];
                float2 o; o.x = qv.x + v0; o.y = qv.y + v1;
                *(float2*)&out[(size_t)r * DDIM + c] = o;
            }
}

// ---------------- fused flash attention (2-stage pipelined, ldmatrix) --------
// Largest-first scheduling; exp2-domain softmax (MUFU.EX2); masked-tile fast path.
__global__ __launch_bounds__(256) void k_flash(const unsigned char* __restrict__ maskRaw)
{
    const int qt = (int)gridDim.x - 1 - (int)blockIdx.x;   // big CTAs first
    const int bh = blockIdx.y;
    const int b = bh >> 4, h = bh & 15;

    extern __shared__ bf16 sm[];
    __shared__ unsigned char mk[2][128];

    const int t = threadIdx.x, lane = t & 31, w = t >> 5;
    const int grp = lane >> 2, tid4 = lane & 3;
    const int useByte = g_maskByte;

    const int kRow = (lane & 7) + ((lane >> 4) << 3);
    const int kCol = (((lane >> 3) & 1) << 3);
    const int vRow = (lane & 15);
    const int vCol = ((lane >> 4) << 3);

    // scores scaled by C = 1/sqrt(128) * log2(e); all exponentials are exp2.
    const float C = 0.088388347648318447f * 1.4426950408889634f;

    // --- stage Q tile through stage-0 area, extract persistent A-fragments ---
    {
        bf16* SQ = sm;
        const bf16* Qg = g_Q + ((size_t)(b * TQS + qt * 128)) * IDIM + h * HDIM;
#pragma unroll
        for (int i = 0; i < 8; i++) {
            int idx = t + i * 256;
            int r = idx >> 4;
            int c = (idx & 15) * 8;
            *(float4*)(SQ + r * FST + c) = *(const float4*)(Qg + (size_t)r * IDIM + c);
        }
    }
    __syncthreads();
    uint32_t qf[8][4];
    {
        const bf16* SQ = sm;
        const int row = w * 16 + (lane & 15);
#pragma unroll
        for (int kc = 0; kc < 8; kc++)
            ldsm_x4(qf[kc], s2u(SQ + row * FST + kc * 16 + ((lane >> 4) << 3)));
    }
    __syncthreads();

    const bf16* Kb = g_K + ((size_t)(b * TKS)) * IDIM + h * HDIM;
    const bf16* Vb = g_V + ((size_t)(b * TKS)) * IDIM + h * HDIM;

    auto prefetch = [&](int kt, int s) {
        bf16* SK = sm + (size_t)s * (2 * 128 * FST);
        bf16* SV = SK + 128 * FST;
        const bf16* Kg = Kb + (size_t)(kt * 128) * IDIM;
        const bf16* Vg = Vb + (size_t)(kt * 128) * IDIM;
#pragma unroll
        for (int i = 0; i < 8; i++) {
            int idx = t + i * 256;
            int r = idx >> 4;
            int c = (idx & 15) * 8;
            cpa16(&SK[r * FST + c], Kg + (size_t)r * IDIM + c);
            cpa16(&SV[r * FST + c], Vg + (size_t)r * IDIM + c);
        }
        if (t < 128) {
            int k = kt * 128 + t;
            int mv = useByte ? (int)maskRaw[(size_t)b * TKS + k]
                             : ((const int*)maskRaw)[(size_t)b * TKS + k];
            mk[s][t] = (unsigned char)(mv != 0);
        }
        CP_COMMIT();
    };

    float m0 = -INFINITY, m1 = -INFINITY, l0 = 0.f, l1 = 0.f;
    float ao[16][4];
#pragma unroll
    for (int ni = 0; ni < 16; ni++)
#pragma unroll
        for (int j = 0; j < 4; j++) ao[ni][j] = 0.f;

    const int q0 = qt * 128 + w * 16 + grp;
    const int q1 = q0 + 8;

    prefetch(0, 0);
    int buf = 0;

    for (int kt = 0; kt <= qt; kt++) {
        if (kt < qt) {
            prefetch(kt + 1, buf ^ 1);
            CP_WAIT(1);
        } else {
            CP_WAIT(0);
        }
        __syncthreads();

        const bf16* SK = sm + (size_t)buf * (2 * 128 * FST);
        const bf16* SV = SK + 128 * FST;

        // --- S = Q K^T (16x128 per warp) ---
        float as_[16][4];
#pragma unroll
        for (int ni = 0; ni < 16; ni++)
#pragma unroll
            for (int j = 0; j < 4; j++) as_[ni][j] = 0.f;
#pragma unroll
        for (int kc = 0; kc < 8; kc++) {
#pragma unroll
            for (int ni = 0; ni < 16; ni += 2) {
                uint32_t bq[4];
                int n = ni * 8 + kRow;
                ldsm_x4(bq, s2u(SK + n * FST + kc * 16 + kCol));
                mma16816(as_[ni],     qf[kc], bq);
                mma16816(as_[ni + 1], qf[kc], bq + 2);
            }
        }

        // --- tile classification: clean (no causal, no padding) vs heavy ---
        bool heavy = (kt == qt);
        {
            uint32_t m4 = ((const uint32_t*)mk[buf])[lane];
            if (__ballot_sync(0xffffffffu, m4 != 0)) heavy = true;
        }

        // --- scale (+ masks on heavy path); row max (exp2 domain) ---
        float tm0 = -INFINITY, tm1 = -INFINITY;
        if (!heavy) {
#pragma unroll
            for (int ni = 0; ni < 16; ni++) {
                float s0 = as_[ni][0] * C;
                float s1 = as_[ni][1] * C;
                float s2 = as_[ni][2] * C;
                float s3 = as_[ni][3] * C;
                as_[ni][0] = s0; as_[ni][1] = s1; as_[ni][2] = s2; as_[ni][3] = s3;
                tm0 = fmaxf(tm0, fmaxf(s0, s1));
                tm1 = fmaxf(tm1, fmaxf(s2, s3));
            }
        } else {
#pragma unroll
            for (int ni = 0; ni < 16; ni++) {
                int kc0 = ni * 8 + tid4 * 2;
                int kg = kt * 128 + kc0;
                bool pm0 = mk[buf][kc0] != 0, pm1 = mk[buf][kc0 + 1] != 0;
                float s0 = (kg     > q0 || pm0) ? -INFINITY : as_[ni][0] * C;
                float s1 = (kg + 1 > q0 || pm1) ? -INFINITY : as_[ni][1] * C;
                float s2 = (kg     > q1 || pm0) ? -INFINITY : as_[ni][2] * C;
                float s3 = (kg + 1 > q1 || pm1) ? -INFINITY : as_[ni][3] * C;
                as_[ni][0] = s0; as_[ni][1] = s1; as_[ni][2] = s2; as_[ni][3] = s3;
                tm0 = fmaxf(tm0, fmaxf(s0, s1));
                tm1 = fmaxf(tm1, fmaxf(s2, s3));
            }
        }
        tm0 = fmaxf(tm0, __shfl_xor_sync(0xffffffffu, tm0, 1));
        tm0 = fmaxf(tm0, __shfl_xor_sync(0xffffffffu, tm0, 2));
        tm1 = fmaxf(tm1, __shfl_xor_sync(0xffffffffu, tm1, 1));
        tm1 = fmaxf(tm1, __shfl_xor_sync(0xffffffffu, tm1, 2));

        // --- online softmax update (exp2 domain, MUFU.EX2) ---
        float mn0 = fmaxf(m0, tm0), mn1 = fmaxf(m1, tm1);
        float f0 = ex2(m0 - mn0), f1 = ex2(m1 - mn1);
        m0 = mn0; m1 = mn1;

        float rs0 = 0.f, rs1 = 0.f;
#pragma unroll
        for (int ni = 0; ni < 16; ni++) {
            float p0 = ex2(as_[ni][0] - mn0);
            float p1 = ex2(as_[ni][1] - mn0);
            float p2 = ex2(as_[ni][2] - mn1);
            float p3 = ex2(as_[ni][3] - mn1);
            as_[ni][0] = p0; as_[ni][1] = p1; as_[ni][2] = p2; as_[ni][3] = p3;
            rs0 += p0 + p1;
            rs1 += p2 + p3;
        }
        rs0 += __shfl_xor_sync(0xffffffffu, rs0, 1);
        rs0 += __shfl_xor_sync(0xffffffffu, rs0, 2);
        rs1 += __shfl_xor_sync(0xffffffffu, rs1, 1);
        rs1 += __shfl_xor_sync(0xffffffffu, rs1, 2);
        l0 = l0 * f0 + rs0;
        l1 = l1 * f1 + rs1;

        // --- rescale O accumulator ---
#pragma unroll
        for (int ni = 0; ni < 16; ni++) {
            ao[ni][0] *= f0; ao[ni][1] *= f0;
            ao[ni][2] *= f1; ao[ni][3] *= f1;
        }

        // --- O += P V (P in regs; V via ldmatrix.trans) ---
#pragma unroll
        for (int kc = 0; kc < 8; kc++) {
            uint32_t pf[4];
            __nv_bfloat162 h0 = __float22bfloat162_rn(make_float2(as_[2*kc][0],   as_[2*kc][1]));
            __nv_bfloat162 h1 = __float22bfloat162_rn(make_float2(as_[2*kc][2],   as_[2*kc][3]));
            __nv_bfloat162 h2 = __float22bfloat162_rn(make_float2(as_[2*kc+1][0], as_[2*kc+1][1]));
            __nv_bfloat162 h3 = __float22bfloat162_rn(make_float2(as_[2*kc+1][2], as_[2*kc+1][3]));
            pf[0] = *(uint32_t*)&h0;
            pf[1] = *(uint32_t*)&h1;
            pf[2] = *(uint32_t*)&h2;
            pf[3] = *(uint32_t*)&h3;
#pragma unroll
            for (int ni = 0; ni < 16; ni += 2) {
                uint32_t bq[4];
                int row = kc * 16 + vRow;
                ldsm_x4_t(bq, s2u(SV + row * FST + ni * 8 + vCol));
                mma16816(ao[ni],     pf, bq);
                mma16816(ao[ni + 1], pf, bq + 2);
            }
        }
        __syncthreads();
        buf ^= 1;
    }

    // --- normalize and write ctx (bf16) ---
    const float inv0 = 1.f / l0, inv1 = 1.f / l1;
    bf16* Cg = g_Ctx + ((size_t)(b * TQS + qt * 128 + w * 16)) * IDIM + h * HDIM;
#pragma unroll
    for (int ni = 0; ni < 16; ni++) {
        int c = ni * 8 + tid4 * 2;
        __nv_bfloat162 o0 = __float22bfloat162_rn(make_float2(ao[ni][0] * inv0, ao[ni][1] * inv0));
        __nv_bfloat162 o1 = __float22bfloat162_rn(make_float2(ao[ni][2] * inv1, ao[ni][3] * inv1));
        *(__nv_bfloat162*)(Cg + (size_t)grp * IDIM + c)       = o0;
        *(__nv_bfloat162*)(Cg + (size_t)(grp + 8) * IDIM + c) = o1;
    }
}

// fused fp32 -> bf16 conversion over all 6 arrays in one launch
struct CvtArgs {
    const float* src[6];
    bf16* dst[6];
    int end[6];   // cumulative block ends
};
__global__ __launch_bounds__(256) void k_cvt_all(CvtArgs a)
{
    int blk = blockIdx.x;
    int seg = 0;
#pragma unroll
    for (int s = 0; s < 5; s++) seg += (blk >= a.end[s]) ? 1 : 0;
    int base = seg ? a.end[seg - 1] : 0;
    int i = (((blk - base) * 256) + threadIdx.x) * 4;
    float4 v = *(const float4*)(a.src[seg] + i);
    __nv_bfloat162 x, y;
    x.x = __float2bfloat16(v.x); x.y = __float2bfloat16(v.y);
    y.x = __float2bfloat16(v.z); y.y = __float2bfloat16(v.w);
    *(__nv_bfloat162*)(a.dst[seg] + i)     = x;
    *(__nv_bfloat162*)(a.dst[seg] + i + 2) = y;
}

// detect mask storage layout: byte 4095 == 1 => 1-byte bool; == 0 => int32
__global__ void k_detect(const unsigned char* __restrict__ mask)
{
    g_maskByte = (mask[(size_t)NBATCH * TKS - 1] != 0) ? 1 : 0;
}

// ---------------- launch -----------------------------------------------------
extern "C" void kernel_launch(void* const* d_in, const int* in_sizes, int n_in,
                              void* d_out, int out_size)
{
    const float* query = (const float*)d_in[0];
    const float* kv    = (const float*)d_in[1];
    const unsigned char* mask = (const unsigned char*)d_in[2];
    const float* Wq = (const float*)d_in[3];
    const float* bq = (const float*)d_in[4];
    const float* Wk = (const float*)d_in[5];
    const float* bk = (const float*)d_in[6];
    const float* Wv = (const float*)d_in[7];
    const float* bv = (const float*)d_in[8];
    const float* Wo = (const float*)d_in[9];
    const float* bo = (const float*)d_in[10];
    const float* gate = (const float*)d_in[11];
    float* out = (float*)d_out;

    // symbol addresses
    bf16 *pXq, *pXkv, *pWq, *pWk, *pWv, *pWo, *pQ, *pK, *pV;
    cudaGetSymbolAddress((void**)&pXq,  g_Xq);
    cudaGetSymbolAddress((void**)&pXkv, g_Xkv);
    cudaGetSymbolAddress((void**)&pWq,  g_Wq);
    cudaGetSymbolAddress((void**)&pWk,  g_Wk);
    cudaGetSymbolAddress((void**)&pWv,  g_Wv);
    cudaGetSymbolAddress((void**)&pWo,  g_Wo);
    cudaGetSymbolAddress((void**)&pQ,   g_Q);
    cudaGetSymbolAddress((void**)&pK,   g_K);
    cudaGetSymbolAddress((void**)&pV,   g_V);

    static int attrSet = 0;
    const int FLASH_SMEM = 2 * 2 * 128 * FST * (int)sizeof(bf16);  // 139264
    if (!attrSet) {
        cudaFuncSetAttribute(k_flash, cudaFuncAttributeMaxDynamicSharedMemorySize, FLASH_SMEM);
        cudaFuncSetAttribute(k_qkv,   cudaFuncAttributeMaxDynamicSharedMemorySize, GEMM_SMEM);
        cudaFuncSetAttribute(k_out,   cudaFuncAttributeMaxDynamicSharedMemorySize, GEMM_SMEM);
        attrSet = 1;
    }

    k_detect<<<1, 1>>>(mask);

    // fused conversions: tokens (2 x 8.4M) + weights (4 x 4.2M)
    {
        CvtArgs a;
        a.src[0] = query; a.dst[0] = pXq;
        a.src[1] = kv;    a.dst[1] = pXkv;
        a.src[2] = Wq;    a.dst[2] = pWq;
        a.src[3] = Wk;    a.dst[3] = pWk;
        a.src[4] = Wv;    a.dst[4] = pWv;
        a.src[5] = Wo;    a.dst[5] = pWo;
        const int nTokB = NBATCH * TQS * DDIM / 1024;  // 8192 blocks
        const int nWB   = IDIM * DDIM / 1024;          // 4096 blocks
        int e = 0;
        e += nTokB; a.end[0] = e;
        e += nTokB; a.end[1] = e;
        e += nWB;   a.end[2] = e;
        e += nWB;   a.end[3] = e;
        e += nWB;   a.end[4] = e;
        e += nWB;   a.end[5] = e;
        k_cvt_all<<<e, 256>>>(a);
    }

    // fused Q/K/V projections: one launch, z in {0,1,2}
    {
        QkvArgs qa;
        qa.X[0] = pXq;  qa.W[0] = pWq; qa.bias[0] = bq; qa.out[0] = pQ;
        qa.X[1] = pXkv; qa.W[1] = pWk; qa.bias[1] = bk; qa.out[1] = pK;
        qa.X[2] = pXkv; qa.W[2] = pWv; qa.bias[2] = bv; qa.out[2] = pV;
        dim3 g(IDIM / BN, NBATCH * TQS / BM, 3);       // (16, 32, 3)
        k_qkv<<<g, 256, GEMM_SMEM>>>(qa);
    }

    k_flash<<<dim3(TQS / 128, NBH), 256, FLASH_SMEM>>>(mask);

    k_out<<<dim3(DDIM / BN, NBATCH * TQS / BM), 256, GEMM_SMEM>>>(query, bo, gate, out);
}

// round 16
// speedup vs baseline: 1.1485x; 1.0558x over previous
#include <cuda_runtime.h>
#include <cuda_bf16.h>
#include <cstdint>
#include <math.h>

// Problem constants (fixed by reference setup)
#define TQS 2048
#define TKS 2048
#define DDIM 2048
#define IDIM 2048
#define NHEAD 16
#define HDIM 128
#define NBATCH 2
#define NBH (NBATCH*NHEAD)

typedef __nv_bfloat16 bf16;

// ---------------- scratch (device globals; no runtime allocation) -----------
__device__ bf16  g_Xq [(size_t)NBATCH*TQS*DDIM];
__device__ bf16  g_Xkv[(size_t)NBATCH*TKS*DDIM];
__device__ bf16  g_Wq [(size_t)IDIM*DDIM];
__device__ bf16  g_Wk [(size_t)IDIM*DDIM];
__device__ bf16  g_Wv [(size_t)IDIM*DDIM];
__device__ bf16  g_Wo [(size_t)DDIM*IDIM];
__device__ bf16  g_Q  [(size_t)NBATCH*TQS*IDIM];
__device__ bf16  g_K  [(size_t)NBATCH*TKS*IDIM];
__device__ bf16  g_V  [(size_t)NBATCH*TKS*IDIM];
__device__ bf16  g_Ctx[(size_t)NBATCH*TQS*IDIM];
__device__ int   g_maskByte;

// ---------------- helpers -----------------------------------------------------
__device__ __forceinline__ uint32_t s2u(const void* p) {
    return (uint32_t)__cvta_generic_to_shared(p);
}
__device__ __forceinline__ void cpa16(void* dst, const void* src) {
    uint32_t d = s2u(dst);
    asm volatile("cp.async.cg.shared.global [%0], [%1], 16;\n" :: "r"(d), "l"(src));
}
#define CP_COMMIT() asm volatile("cp.async.commit_group;\n" ::: "memory")
#define CP_WAIT(N)  asm volatile("cp.async.wait_group %0;\n" :: "n"(N) : "memory")

// single-instruction exp2 (MUFU.EX2); input <= 0 or -inf in our uses
__device__ __forceinline__ float ex2(float x) {
    float y;
    asm("ex2.approx.ftz.f32 %0, %1;" : "=f"(y) : "f"(x));
    return y;
}

__device__ __forceinline__ void mma16816(float c[4], const uint32_t a[4], const uint32_t b[2]) {
    asm volatile(
        "mma.sync.aligned.m16n8k16.row.col.f32.bf16.bf16.f32 "
        "{%0,%1,%2,%3}, {%4,%5,%6,%7}, {%8,%9}, {%0,%1,%2,%3};\n"
        : "+f"(c[0]), "+f"(c[1]), "+f"(c[2]), "+f"(c[3])
        : "r"(a[0]), "r"(a[1]), "r"(a[2]), "r"(a[3]), "r"(b[0]), "r"(b[1]));
}
__device__ __forceinline__ void ldsm_x4(uint32_t r[4], uint32_t addr) {
    asm volatile("ldmatrix.sync.aligned.m8n8.x4.shared.b16 {%0,%1,%2,%3}, [%4];"
        : "=r"(r[0]), "=r"(r[1]), "=r"(r[2]), "=r"(r[3]) : "r"(addr));
}
__device__ __forceinline__ void ldsm_x4_t(uint32_t r[4], uint32_t addr) {
    asm volatile("ldmatrix.sync.aligned.m8n8.x4.trans.shared.b16 {%0,%1,%2,%3}, [%4];"
        : "=r"(r[0]), "=r"(r[1]), "=r"(r[2]), "=r"(r[3]) : "r"(addr));
}

// ---------------- GEMM core: C(128x128) += A(128xK) * B(128xK)^T ------------
// 4-stage cp.async pipeline, ONE __syncthreads per TWO K-steps. 2 CTAs/SM.
#define BM 128
#define BN 128
#define BK 32
#define SAST 40   // padded smem stride (bf16); LDSM conflict-free
#define FST 136   // padded smem stride for flash tiles
#define GSTAGE (2 * 128 * SAST)                      // bf16 elems per stage (A+B)
#define GEMM_SMEM (4 * GSTAGE * (int)sizeof(bf16))   // 81920 B

__device__ __forceinline__ void gemm_mma_step(
    const bf16* __restrict__ SA, const bf16* __restrict__ SB,
    int wm, int wn, int aRow, int aCol, int bRow, int bCol,
    float (&acc)[4][4][4])
{
#pragma unroll
    for (int kk = 0; kk < BK; kk += 16) {
        uint32_t af[4][4];
#pragma unroll
        for (int mi = 0; mi < 4; mi++) {
            int row = wm * 64 + mi * 16 + aRow;
            ldsm_x4(af[mi], s2u(SA + row * SAST + kk + aCol));
        }
        uint32_t bq[2][4];
#pragma unroll
        for (int p = 0; p < 2; p++) {
            int n = wn * 32 + p * 16 + bRow;
            ldsm_x4(bq[p], s2u(SB + n * SAST + kk + bCol));
        }
#pragma unroll
        for (int mi = 0; mi < 4; mi++)
#pragma unroll
            for (int ni = 0; ni < 4; ni++)
                mma16816(acc[mi][ni], af[mi], &bq[ni >> 1][(ni & 1) * 2]);
    }
}

__device__ __forceinline__ void gemm_core4(
    const bf16* __restrict__ A, int lda,
    const bf16* __restrict__ Bm, int ldb,
    int nSteps, float (&acc)[4][4][4], bf16* __restrict__ smem)
{
    const int t    = threadIdx.x;
    const int lane = t & 31;
    const int warp = t >> 5;
    const int wm   = warp & 1;
    const int wn   = warp >> 1;

    const int aRow = (lane & 15);
    const int aCol = ((lane >> 4) << 3);
    const int bRow = (lane & 7) + ((lane >> 4) << 3);
    const int bCol = (((lane >> 3) & 1) << 3);

    auto loadStage = [&](int k0, int st) {
        bf16* SA = smem + st * GSTAGE;
        bf16* SB = SA + 128 * SAST;
#pragma unroll
        for (int i = 0; i < 2; i++) {
            int idx = t + i * 256;
            int r = idx >> 2;
            int c = (idx & 3) << 3;
            cpa16(&SA[r * SAST + c], A  + (size_t)r * lda + k0 + c);
            cpa16(&SB[r * SAST + c], Bm + (size_t)r * ldb + k0 + c);
        }
        CP_COMMIT();
    };

    loadStage(0, 0);
    loadStage(BK, 1);

    // nSteps is even (K multiples of 64)
    for (int s = 0; s < nSteps; s += 2) {
        CP_WAIT(0);
        __syncthreads();
        if (s + 2 < nSteps) loadStage((s + 2) * BK, (s + 2) & 3);
        if (s + 3 < nSteps) loadStage((s + 3) * BK, (s + 3) & 3);

        const bf16* SA0 = smem + (s & 3) * GSTAGE;
        gemm_mma_step(SA0, SA0 + 128 * SAST, wm, wn, aRow, aCol, bRow, bCol, acc);
        const bf16* SA1 = smem + ((s + 1) & 3) * GSTAGE;
        gemm_mma_step(SA1, SA1 + 128 * SAST, wm, wn, aRow, aCol, bRow, bCol, acc);
    }
}

#define GEMM_PROLOG()                              \
    float acc[4][4][4];                            \
    _Pragma("unroll") for (int a_=0;a_<4;a_++)     \
    _Pragma("unroll") for (int b_=0;b_<4;b_++)     \
    _Pragma("unroll") for (int c_=0;c_<4;c_++) acc[a_][b_][c_] = 0.f;

#define EPI_VARS()                                  \
    const int lane = threadIdx.x & 31;              \
    const int warp = threadIdx.x >> 5;              \
    const int wm = warp & 1, wn = warp >> 1;        \
    const int grp = lane >> 2, tid4 = lane & 3;

// ---------------- fused Q/K/V projection (blockIdx.z selects matrix) ---------
struct QkvArgs {
    const bf16* X[3];
    const bf16* W[3];
    const float* bias[3];
    bf16* out[3];
};
__global__ __launch_bounds__(256, 2) void k_qkv(QkvArgs a)
{
    extern __shared__ bf16 dsm[];
    const int z = blockIdx.z;
    const int m0 = blockIdx.y * BM;
    const int n0 = blockIdx.x * BN;
    const bf16* X = a.X[z];
    const bf16* W = a.W[z];
    const float* bias = a.bias[z];
    bf16* Cout = a.out[z];

    GEMM_PROLOG();
    gemm_core4(X + (size_t)m0 * DDIM, DDIM, W + (size_t)n0 * DDIM, DDIM,
               DDIM / BK, acc, dsm);
    EPI_VARS();
#pragma unroll
    for (int mi = 0; mi < 4; mi++)
#pragma unroll
        for (int ni = 0; ni < 4; ni++)
#pragma unroll
            for (int hh = 0; hh < 2; hh++) {
                int r = m0 + wm * 64 + mi * 16 + grp + hh * 8;
                int c = n0 + wn * 32 + ni * 8 + tid4 * 2;
                float v0 = acc[mi][ni][hh * 2 + 0] + bias[c];
                float v1 = acc[mi][ni][hh * 2 + 1] + bias[c + 1];
                __nv_bfloat162 o;
                o.x = __float2bfloat16(v0);
                o.y = __float2bfloat16(v1);
                *(__nv_bfloat162*)&Cout[(size_t)r * IDIM + c] = o;
            }
}

// out = query + (ctx * Wo^T + bo) * sigmoid(gate)
__global__ __launch_bounds__(256, 2) void k_out(
    const float* __restrict__ query, const float* __restrict__ bo,
    const float* __restrict__ gate, float* __restrict__ out)
{
    extern __shared__ bf16 dsm[];
    const int m0 = blockIdx.y * BM;
    const int n0 = blockIdx.x * BN;
    const float L2E = 1.4426950408889634f;
    GEMM_PROLOG();
    gemm_core4(g_Ctx + (size_t)m0 * IDIM, IDIM, g_Wo + (size_t)n0 * IDIM, IDIM,
               IDIM / BK, acc, dsm);
    EPI_VARS();
#pragma unroll
    for (int mi = 0; mi < 4; mi++)
#pragma unroll
        for (int ni = 0; ni < 4; ni++)
#pragma unroll
            for (int hh = 0; hh < 2; hh++) {
                int r = m0 + wm * 64 + mi * 16 + grp + hh * 8;
                int c = n0 + wn * 32 + ni * 8 + tid4 * 2;
                float g0 = 1.f / (1.f + ex2(-gate[c]     * L2E));
                float g1 = 1.f / (1.f + ex2(-gate[c + 1] * L2E));
                float v0 = (acc[mi][ni][hh * 2 + 0] + bo[c])     * g0;
                float v1 = (acc[mi][ni][hh * 2 + 1] + bo[c + 1]) * g1;
                float2 qv = *(const float2*)&query[(size_t)r * DDIM + c];
                float2 o; o.x = qv.x + v0; o.y = qv.y + v1;
                *(float2*)&out[(size_t)r * DDIM + c] = o;
            }
}

// ---------------- fused flash attention (3-stage pipelined, ldmatrix) --------
// Largest-first scheduling; exp2-domain softmax (MUFU.EX2); masked-tile fast
// path; warp-uniform O-rescale skip.
__global__ __launch_bounds__(256) void k_flash(const unsigned char* __restrict__ maskRaw)
{
    const int qt = (int)gridDim.x - 1 - (int)blockIdx.x;   // big CTAs first
    const int bh = blockIdx.y;
    const int b = bh >> 4, h = bh & 15;

    extern __shared__ bf16 sm[];
    __shared__ unsigned char mk[3][128];

    const int t = threadIdx.x, lane = t & 31, w = t >> 5;
    const int grp = lane >> 2, tid4 = lane & 3;
    const int useByte = g_maskByte;

    const int kRow = (lane & 7) + ((lane >> 4) << 3);
    const int kCol = (((lane >> 3) & 1) << 3);
    const int vRow = (lane & 15);
    const int vCol = ((lane >> 4) << 3);

    // scores scaled by C = 1/sqrt(128) * log2(e); all exponentials are exp2.
    const float C = 0.088388347648318447f * 1.4426950408889634f;

    // --- stage Q tile through stage-0 area, extract persistent A-fragments ---
    {
        bf16* SQ = sm;
        const bf16* Qg = g_Q + ((size_t)(b * TQS + qt * 128)) * IDIM + h * HDIM;
#pragma unroll
        for (int i = 0; i < 8; i++) {
            int idx = t + i * 256;
            int r = idx >> 4;
            int c = (idx & 15) * 8;
            *(float4*)(SQ + r * FST + c) = *(const float4*)(Qg + (size_t)r * IDIM + c);
        }
    }
    __syncthreads();
    uint32_t qf[8][4];
    {
        const bf16* SQ = sm;
        const int row = w * 16 + (lane & 15);
#pragma unroll
        for (int kc = 0; kc < 8; kc++)
            ldsm_x4(qf[kc], s2u(SQ + row * FST + kc * 16 + ((lane >> 4) << 3)));
    }
    __syncthreads();

    const bf16* Kb = g_K + ((size_t)(b * TKS)) * IDIM + h * HDIM;
    const bf16* Vb = g_V + ((size_t)(b * TKS)) * IDIM + h * HDIM;

    auto prefetch = [&](int kt, int s) {
        bf16* SK = sm + (size_t)s * (2 * 128 * FST);
        bf16* SV = SK + 128 * FST;
        const bf16* Kg = Kb + (size_t)(kt * 128) * IDIM;
        const bf16* Vg = Vb + (size_t)(kt * 128) * IDIM;
#pragma unroll
        for (int i = 0; i < 8; i++) {
            int idx = t + i * 256;
            int r = idx >> 4;
            int c = (idx & 15) * 8;
            cpa16(&SK[r * FST + c], Kg + (size_t)r * IDIM + c);
            cpa16(&SV[r * FST + c], Vg + (size_t)r * IDIM + c);
        }
        if (t < 128) {
            int k = kt * 128 + t;
            int mv = useByte ? (int)maskRaw[(size_t)b * TKS + k]
                             : ((const int*)maskRaw)[(size_t)b * TKS + k];
            mk[s][t] = (unsigned char)(mv != 0);
        }
        CP_COMMIT();
    };

    float m0 = -INFINITY, m1 = -INFINITY, l0 = 0.f, l1 = 0.f;
    float ao[16][4];
#pragma unroll
    for (int ni = 0; ni < 16; ni++)
#pragma unroll
        for (int j = 0; j < 4; j++) ao[ni][j] = 0.f;

    const int q0 = qt * 128 + w * 16 + grp;
    const int q1 = q0 + 8;

    prefetch(0, 0);
    if (qt >= 1) prefetch(1, 1);

    for (int kt = 0; kt <= qt; kt++) {
        if (kt + 2 <= qt) {
            prefetch(kt + 2, (kt + 2) % 3);
            CP_WAIT(2);
        } else if (kt + 1 <= qt) {
            CP_WAIT(1);
        } else {
            CP_WAIT(0);
        }
        __syncthreads();

        const int buf = kt % 3;
        const bf16* SK = sm + (size_t)buf * (2 * 128 * FST);
        const bf16* SV = SK + 128 * FST;

        // --- S = Q K^T (16x128 per warp) ---
        float as_[16][4];
#pragma unroll
        for (int ni = 0; ni < 16; ni++)
#pragma unroll
            for (int j = 0; j < 4; j++) as_[ni][j] = 0.f;
#pragma unroll
        for (int kc = 0; kc < 8; kc++) {
#pragma unroll
            for (int ni = 0; ni < 16; ni += 2) {
                uint32_t bq[4];
                int n = ni * 8 + kRow;
                ldsm_x4(bq, s2u(SK + n * FST + kc * 16 + kCol));
                mma16816(as_[ni],     qf[kc], bq);
                mma16816(as_[ni + 1], qf[kc], bq + 2);
            }
        }

        // --- tile classification: clean (no causal, no padding) vs heavy ---
        bool heavy = (kt == qt);
        {
            uint32_t m4 = ((const uint32_t*)mk[buf])[lane];
            if (__ballot_sync(0xffffffffu, m4 != 0)) heavy = true;
        }

        // --- scale (+ masks on heavy path); row max (exp2 domain) ---
        float tm0 = -INFINITY, tm1 = -INFINITY;
        if (!heavy) {
#pragma unroll
            for (int ni = 0; ni < 16; ni++) {
                float s0 = as_[ni][0] * C;
                float s1 = as_[ni][1] * C;
                float s2 = as_[ni][2] * C;
                float s3 = as_[ni][3] * C;
                as_[ni][0] = s0; as_[ni][1] = s1; as_[ni][2] = s2; as_[ni][3] = s3;
                tm0 = fmaxf(tm0, fmaxf(s0, s1));
                tm1 = fmaxf(tm1, fmaxf(s2, s3));
            }
        } else {
#pragma unroll
            for (int ni = 0; ni < 16; ni++) {
                int kc0 = ni * 8 + tid4 * 2;
                int kg = kt * 128 + kc0;
                bool pm0 = mk[buf][kc0] != 0, pm1 = mk[buf][kc0 + 1] != 0;
                float s0 = (kg     > q0 || pm0) ? -INFINITY : as_[ni][0] * C;
                float s1 = (kg + 1 > q0 || pm1) ? -INFINITY : as_[ni][1] * C;
                float s2 = (kg     > q1 || pm0) ? -INFINITY : as_[ni][2] * C;
                float s3 = (kg + 1 > q1 || pm1) ? -INFINITY : as_[ni][3] * C;
                as_[ni][0] = s0; as_[ni][1] = s1; as_[ni][2] = s2; as_[ni][3] = s3;
                tm0 = fmaxf(tm0, fmaxf(s0, s1));
                tm1 = fmaxf(tm1, fmaxf(s2, s3));
            }
        }
        tm0 = fmaxf(tm0, __shfl_xor_sync(0xffffffffu, tm0, 1));
        tm0 = fmaxf(tm0, __shfl_xor_sync(0xffffffffu, tm0, 2));
        tm1 = fmaxf(tm1, __shfl_xor_sync(0xffffffffu, tm1, 1));
        tm1 = fmaxf(tm1, __shfl_xor_sync(0xffffffffu, tm1, 2));

        // --- online softmax update (exp2 domain, MUFU.EX2) ---
        const bool need = (tm0 > m0) || (tm1 > m1);
        const uint32_t vote = __ballot_sync(0xffffffffu, need);
        float mn0 = fmaxf(m0, tm0), mn1 = fmaxf(m1, tm1);

        float rs0, rs1;
        if (vote) {
            float f0 = ex2(m0 - mn0), f1 = ex2(m1 - mn1);
            m0 = mn0; m1 = mn1;
            rs0 = 0.f; rs1 = 0.f;
#pragma unroll
            for (int ni = 0; ni < 16; ni++) {
                float p0 = ex2(as_[ni][0] - mn0);
                float p1 = ex2(as_[ni][1] - mn0);
                float p2 = ex2(as_[ni][2] - mn1);
                float p3 = ex2(as_[ni][3] - mn1);
                as_[ni][0] = p0; as_[ni][1] = p1; as_[ni][2] = p2; as_[ni][3] = p3;
                rs0 += p0 + p1;
                rs1 += p2 + p3;
            }
            // rescale O accumulator
#pragma unroll
            for (int ni = 0; ni < 16; ni++) {
                ao[ni][0] *= f0; ao[ni][1] *= f0;
                ao[ni][2] *= f1; ao[ni][3] *= f1;
            }
            rs0 += __shfl_xor_sync(0xffffffffu, rs0, 1);
            rs0 += __shfl_xor_sync(0xffffffffu, rs0, 2);
            rs1 += __shfl_xor_sync(0xffffffffu, rs1, 1);
            rs1 += __shfl_xor_sync(0xffffffffu, rs1, 2);
            l0 = l0 * f0 + rs0;
            l1 = l1 * f1 + rs1;
        } else {
            // max unchanged for every row in this warp: f == 1 exactly
            rs0 = 0.f; rs1 = 0.f;
#pragma unroll
            for (int ni = 0; ni < 16; ni++) {
                float p0 = ex2(as_[ni][0] - mn0);
                float p1 = ex2(as_[ni][1] - mn0);
                float p2 = ex2(as_[ni][2] - mn1);
                float p3 = ex2(as_[ni][3] - mn1);
                as_[ni][0] = p0; as_[ni][1] = p1; as_[ni][2] = p2; as_[ni][3] = p3;
                rs0 += p0 + p1;
                rs1 += p2 + p3;
            }
            rs0 += __shfl_xor_sync(0xffffffffu, rs0, 1);
            rs0 += __shfl_xor_sync(0xffffffffu, rs0, 2);
            rs1 += __shfl_xor_sync(0xffffffffu, rs1, 1);
            rs1 += __shfl_xor_sync(0xffffffffu, rs1, 2);
            l0 += rs0;
            l1 += rs1;
        }

        // --- O += P V (P in regs; V via ldmatrix.trans) ---
#pragma unroll
        for (int kc = 0; kc < 8; kc++) {
            uint32_t pf[4];
            __nv_bfloat162 h0 = __float22bfloat162_rn(make_float2(as_[2*kc][0],   as_[2*kc][1]));
            __nv_bfloat162 h1 = __float22bfloat162_rn(make_float2(as_[2*kc][2],   as_[2*kc][3]));
            __nv_bfloat162 h2 = __float22bfloat162_rn(make_float2(as_[2*kc+1][0], as_[2*kc+1][1]));
            __nv_bfloat162 h3 = __float22bfloat162_rn(make_float2(as_[2*kc+1][2], as_[2*kc+1][3]));
            pf[0] = *(uint32_t*)&h0;
            pf[1] = *(uint32_t*)&h1;
            pf[2] = *(uint32_t*)&h2;
            pf[3] = *(uint32_t*)&h3;
#pragma unroll
            for (int ni = 0; ni < 16; ni += 2) {
                uint32_t bq[4];
                int row = kc * 16 + vRow;
                ldsm_x4_t(bq, s2u(SV + row * FST + ni * 8 + vCol));
                mma16816(ao[ni],     pf, bq);
                mma16816(ao[ni + 1], pf, bq + 2);
            }
        }
        __syncthreads();
    }

    // --- normalize and write ctx (bf16) ---
    const float inv0 = 1.f / l0, inv1 = 1.f / l1;
    bf16* Cg = g_Ctx + ((size_t)(b * TQS + qt * 128 + w * 16)) * IDIM + h * HDIM;
#pragma unroll
    for (int ni = 0; ni < 16; ni++) {
        int c = ni * 8 + tid4 * 2;
        __nv_bfloat162 o0 = __float22bfloat162_rn(make_float2(ao[ni][0] * inv0, ao[ni][1] * inv0));
        __nv_bfloat162 o1 = __float22bfloat162_rn(make_float2(ao[ni][2] * inv1, ao[ni][3] * inv1));
        *(__nv_bfloat162*)(Cg + (size_t)grp * IDIM + c)       = o0;
        *(__nv_bfloat162*)(Cg + (size_t)(grp + 8) * IDIM + c) = o1;
    }
}

// fused fp32 -> bf16 conversion over all 6 arrays; 2048 floats per block
struct CvtArgs {
    const float* src[6];
    bf16* dst[6];
    int end[6];   // cumulative block ends
};
__global__ __launch_bounds__(256) void k_cvt_all(CvtArgs a)
{
    int blk = blockIdx.x;
    int seg = 0;
#pragma unroll
    for (int s = 0; s < 5; s++) seg += (blk >= a.end[s]) ? 1 : 0;
    int base = seg ? a.end[seg - 1] : 0;
    int i0 = (blk - base) * 2048 + threadIdx.x * 4;
#pragma unroll
    for (int rep = 0; rep < 2; rep++) {
        int i = i0 + rep * 1024;
        float4 v = *(const float4*)(a.src[seg] + i);
        __nv_bfloat162 x, y;
        x.x = __float2bfloat16(v.x); x.y = __float2bfloat16(v.y);
        y.x = __float2bfloat16(v.z); y.y = __float2bfloat16(v.w);
        *(__nv_bfloat162*)(a.dst[seg] + i)     = x;
        *(__nv_bfloat162*)(a.dst[seg] + i + 2) = y;
    }
}

// detect mask storage layout: byte 4095 == 1 => 1-byte bool; == 0 => int32
__global__ void k_detect(const unsigned char* __restrict__ mask)
{
    g_maskByte = (mask[(size_t)NBATCH * TKS - 1] != 0) ? 1 : 0;
}

// ---------------- launch -----------------------------------------------------
extern "C" void kernel_launch(void* const* d_in, const int* in_sizes, int n_in,
                              void* d_out, int out_size)
{
    const float* query = (const float*)d_in[0];
    const float* kv    = (const float*)d_in[1];
    const unsigned char* mask = (const unsigned char*)d_in[2];
    const float* Wq = (const float*)d_in[3];
    const float* bq = (const float*)d_in[4];
    const float* Wk = (const float*)d_in[5];
    const float* bk = (const float*)d_in[6];
    const float* Wv = (const float*)d_in[7];
    const float* bv = (const float*)d_in[8];
    const float* Wo = (const float*)d_in[9];
    const float* bo = (const float*)d_in[10];
    const float* gate = (const float*)d_in[11];
    float* out = (float*)d_out;

    // symbol addresses
    bf16 *pXq, *pXkv, *pWq, *pWk, *pWv, *pWo, *pQ, *pK, *pV;
    cudaGetSymbolAddress((void**)&pXq,  g_Xq);
    cudaGetSymbolAddress((void**)&pXkv, g_Xkv);
    cudaGetSymbolAddress((void**)&pWq,  g_Wq);
    cudaGetSymbolAddress((void**)&pWk,  g_Wk);
    cudaGetSymbolAddress((void**)&pWv,  g_Wv);
    cudaGetSymbolAddress((void**)&pWo,  g_Wo);
    cudaGetSymbolAddress((void**)&pQ,   g_Q);
    cudaGetSymbolAddress((void**)&pK,   g_K);
    cudaGetSymbolAddress((void**)&pV,   g_V);

    static int attrSet = 0;
    const int FLASH_SMEM = 3 * 2 * 128 * FST * (int)sizeof(bf16);  // 208896
    if (!attrSet) {
        cudaFuncSetAttribute(k_flash, cudaFuncAttributeMaxDynamicSharedMemorySize, FLASH_SMEM);
        cudaFuncSetAttribute(k_qkv,   cudaFuncAttributeMaxDynamicSharedMemorySize, GEMM_SMEM);
        cudaFuncSetAttribute(k_out,   cudaFuncAttributeMaxDynamicSharedMemorySize, GEMM_SMEM);
        attrSet = 1;
    }

    k_detect<<<1, 1>>>(mask);

    // fused conversions: tokens (2 x 8.4M) + weights (4 x 4.2M)
    {
        CvtArgs a;
        a.src[0] = query; a.dst[0] = pXq;
        a.src[1] = kv;    a.dst[1] = pXkv;
        a.src[2] = Wq;    a.dst[2] = pWq;
        a.src[3] = Wk;    a.dst[3] = pWk;
        a.src[4] = Wv;    a.dst[4] = pWv;
        a.src[5] = Wo;    a.dst[5] = pWo;
        const int nTokB = NBATCH * TQS * DDIM / 2048;  // 4096 blocks
        const int nWB   = IDIM * DDIM / 2048;          // 2048 blocks
        int e = 0;
        e += nTokB; a.end[0] = e;
        e += nTokB; a.end[1] = e;
        e += nWB;   a.end[2] = e;
        e += nWB;   a.end[3] = e;
        e += nWB;   a.end[4] = e;
        e += nWB;   a.end[5] = e;
        k_cvt_all<<<e, 256>>>(a);
    }

    // fused Q/K/V projections: one launch, z in {0,1,2}
    {
        QkvArgs qa;
        qa.X[0] = pXq;  qa.W[0] = pWq; qa.bias[0] = bq; qa.out[0] = pQ;
        qa.X[1] = pXkv; qa.W[1] = pWk; qa.bias[1] = bk; qa.out[1] = pK;
        qa.X[2] = pXkv; qa.W[2] = pWv; qa.bias[2] = bv; qa.out[2] = pV;
        dim3 g(IDIM / BN, NBATCH * TQS / BM, 3);       // (16, 32, 3)
        k_qkv<<<g, 256, GEMM_SMEM>>>(qa);
    }

    k_flash<<<dim3(TQS / 128, NBH), 256, FLASH_SMEM>>>(mask);

    k_out<<<dim3(DDIM / BN, NBATCH * TQS / BM), 256, GEMM_SMEM>>>(query, bo, gate, out);
}

// round 17
// speedup vs baseline: 1.1535x; 1.0043x over previous
#include <cuda_runtime.h>
#include <cuda_bf16.h>
#include <cstdint>
#include <math.h>

// Problem constants (fixed by reference setup)
#define TQS 2048
#define TKS 2048
#define DDIM 2048
#define IDIM 2048
#define NHEAD 16
#define HDIM 128
#define NBATCH 2
#define NBH (NBATCH*NHEAD)

typedef __nv_bfloat16 bf16;

// ---------------- scratch (device globals; no runtime allocation) -----------
__device__ bf16  g_Xq [(size_t)NBATCH*TQS*DDIM];
__device__ bf16  g_Xkv[(size_t)NBATCH*TKS*DDIM];
__device__ bf16  g_Wq [(size_t)IDIM*DDIM];
__device__ bf16  g_Wk [(size_t)IDIM*DDIM];
__device__ bf16  g_Wv [(size_t)IDIM*DDIM];
__device__ bf16  g_Wo [(size_t)DDIM*IDIM];
__device__ bf16  g_Q  [(size_t)NBATCH*TQS*IDIM];
__device__ bf16  g_K  [(size_t)NBATCH*TKS*IDIM];
__device__ bf16  g_V  [(size_t)NBATCH*TKS*IDIM];
__device__ bf16  g_Ctx[(size_t)NBATCH*TQS*IDIM];
__device__ int   g_maskByte;

// ---------------- helpers -----------------------------------------------------
__device__ __forceinline__ uint32_t s2u(const void* p) {
    return (uint32_t)__cvta_generic_to_shared(p);
}
__device__ __forceinline__ void cpa16(void* dst, const void* src) {
    uint32_t d = s2u(dst);
    asm volatile("cp.async.cg.shared.global [%0], [%1], 16;\n" :: "r"(d), "l"(src));
}
#define CP_COMMIT() asm volatile("cp.async.commit_group;\n" ::: "memory")
#define CP_WAIT(N)  asm volatile("cp.async.wait_group %0;\n" :: "n"(N) : "memory")

// single-instruction exp2 (MUFU.EX2); input <= 0 or -inf in our uses
__device__ __forceinline__ float ex2(float x) {
    float y;
    asm("ex2.approx.ftz.f32 %0, %1;" : "=f"(y) : "f"(x));
    return y;
}

__device__ __forceinline__ void mma16816(float c[4], const uint32_t a[4], const uint32_t b[2]) {
    asm volatile(
        "mma.sync.aligned.m16n8k16.row.col.f32.bf16.bf16.f32 "
        "{%0,%1,%2,%3}, {%4,%5,%6,%7}, {%8,%9}, {%0,%1,%2,%3};\n"
        : "+f"(c[0]), "+f"(c[1]), "+f"(c[2]), "+f"(c[3])
        : "r"(a[0]), "r"(a[1]), "r"(a[2]), "r"(a[3]), "r"(b[0]), "r"(b[1]));
}
__device__ __forceinline__ void ldsm_x4(uint32_t r[4], uint32_t addr) {
    asm volatile("ldmatrix.sync.aligned.m8n8.x4.shared.b16 {%0,%1,%2,%3}, [%4];"
        : "=r"(r[0]), "=r"(r[1]), "=r"(r[2]), "=r"(r[3]) : "r"(addr));
}
__device__ __forceinline__ void ldsm_x4_t(uint32_t r[4], uint32_t addr) {
    asm volatile("ldmatrix.sync.aligned.m8n8.x4.trans.shared.b16 {%0,%1,%2,%3}, [%4];"
        : "=r"(r[0]), "=r"(r[1]), "=r"(r[2]), "=r"(r[3]) : "r"(addr));
}

// ---------------- GEMM core: C(128x128) += A(128xK) * B(128xK)^T ------------
// 4-stage cp.async pipeline, ONE __syncthreads per TWO K-steps. 2 CTAs/SM.
#define BM 128
#define BN 128
#define BK 32
#define SAST 40   // padded smem stride (bf16); LDSM conflict-free
#define FST 136   // padded smem stride for flash tiles
#define GSTAGE (2 * 128 * SAST)                      // bf16 elems per stage (A+B)
#define GEMM_SMEM (4 * GSTAGE * (int)sizeof(bf16))   // 81920 B

__device__ __forceinline__ void gemm_mma_step(
    const bf16* __restrict__ SA, const bf16* __restrict__ SB,
    int wm, int wn, int aRow, int aCol, int bRow, int bCol,
    float (&acc)[4][4][4])
{
#pragma unroll
    for (int kk = 0; kk < BK; kk += 16) {
        uint32_t af[4][4];
#pragma unroll
        for (int mi = 0; mi < 4; mi++) {
            int row = wm * 64 + mi * 16 + aRow;
            ldsm_x4(af[mi], s2u(SA + row * SAST + kk + aCol));
        }
        uint32_t bq[2][4];
#pragma unroll
        for (int p = 0; p < 2; p++) {
            int n = wn * 32 + p * 16 + bRow;
            ldsm_x4(bq[p], s2u(SB + n * SAST + kk + bCol));
        }
#pragma unroll
        for (int mi = 0; mi < 4; mi++)
#pragma unroll
            for (int ni = 0; ni < 4; ni++)
                mma16816(acc[mi][ni], af[mi], &bq[ni >> 1][(ni & 1) * 2]);
    }
}

__device__ __forceinline__ void gemm_core4(
    const bf16* __restrict__ A, int lda,
    const bf16* __restrict__ Bm, int ldb,
    int nSteps, float (&acc)[4][4][4], bf16* __restrict__ smem)
{
    const int t    = threadIdx.x;
    const int lane = t & 31;
    const int warp = t >> 5;
    const int wm   = warp & 1;
    const int wn   = warp >> 1;

    const int aRow = (lane & 15);
    const int aCol = ((lane >> 4) << 3);
    const int bRow = (lane & 7) + ((lane >> 4) << 3);
    const int bCol = (((lane >> 3) & 1) << 3);

    auto loadStage = [&](int k0, int st) {
        bf16* SA = smem + st * GSTAGE;
        bf16* SB = SA + 128 * SAST;
#pragma unroll
        for (int i = 0; i < 2; i++) {
            int idx = t + i * 256;
            int r = idx >> 2;
            int c = (idx & 3) << 3;
            cpa16(&SA[r * SAST + c], A  + (size_t)r * lda + k0 + c);
            cpa16(&SB[r * SAST + c], Bm + (size_t)r * ldb + k0 + c);
        }
        CP_COMMIT();
    };

    loadStage(0, 0);
    loadStage(BK, 1);

    // nSteps is even (K multiples of 64)
    for (int s = 0; s < nSteps; s += 2) {
        CP_WAIT(0);
        __syncthreads();
        if (s + 2 < nSteps) loadStage((s + 2) * BK, (s + 2) & 3);
        if (s + 3 < nSteps) loadStage((s + 3) * BK, (s + 3) & 3);

        const bf16* SA0 = smem + (s & 3) * GSTAGE;
        gemm_mma_step(SA0, SA0 + 128 * SAST, wm, wn, aRow, aCol, bRow, bCol, acc);
        const bf16* SA1 = smem + ((s + 1) & 3) * GSTAGE;
        gemm_mma_step(SA1, SA1 + 128 * SAST, wm, wn, aRow, aCol, bRow, bCol, acc);
    }
}

#define GEMM_PROLOG()                              \
    float acc[4][4][4];                            \
    _Pragma("unroll") for (int a_=0;a_<4;a_++)     \
    _Pragma("unroll") for (int b_=0;b_<4;b_++)     \
    _Pragma("unroll") for (int c_=0;c_<4;c_++) acc[a_][b_][c_] = 0.f;

#define EPI_VARS()                                  \
    const int lane = threadIdx.x & 31;              \
    const int warp = threadIdx.x >> 5;              \
    const int wm = warp & 1, wn = warp >> 1;        \
    const int grp = lane >> 2, tid4 = lane & 3;

// ---------------- fused Q/K/V projection (blockIdx.z selects matrix) ---------
struct QkvArgs {
    const bf16* X[3];
    const bf16* W[3];
    const float* bias[3];
    bf16* out[3];
};
__global__ __launch_bounds__(256, 2) void k_qkv(QkvArgs a)
{
    extern __shared__ bf16 dsm[];
    const int z = blockIdx.z;
    const int m0 = blockIdx.y * BM;
    const int n0 = blockIdx.x * BN;
    const bf16* X = a.X[z];
    const bf16* W = a.W[z];
    const float* bias = a.bias[z];
    bf16* Cout = a.out[z];

    GEMM_PROLOG();
    gemm_core4(X + (size_t)m0 * DDIM, DDIM, W + (size_t)n0 * DDIM, DDIM,
               DDIM / BK, acc, dsm);
    EPI_VARS();
#pragma unroll
    for (int mi = 0; mi < 4; mi++)
#pragma unroll
        for (int ni = 0; ni < 4; ni++)
#pragma unroll
            for (int hh = 0; hh < 2; hh++) {
                int r = m0 + wm * 64 + mi * 16 + grp + hh * 8;
                int c = n0 + wn * 32 + ni * 8 + tid4 * 2;
                float v0 = acc[mi][ni][hh * 2 + 0] + bias[c];
                float v1 = acc[mi][ni][hh * 2 + 1] + bias[c + 1];
                __nv_bfloat162 o;
                o.x = __float2bfloat16(v0);
                o.y = __float2bfloat16(v1);
                *(__nv_bfloat162*)&Cout[(size_t)r * IDIM + c] = o;
            }
}

// out = query + (ctx * Wo^T + bo) * sigmoid(gate)
__global__ __launch_bounds__(256, 2) void k_out(
    const float* __restrict__ query, const float* __restrict__ bo,
    const float* __restrict__ gate, float* __restrict__ out)
{
    extern __shared__ bf16 dsm[];
    const int m0 = blockIdx.y * BM;
    const int n0 = blockIdx.x * BN;
    const float L2E = 1.4426950408889634f;
    GEMM_PROLOG();
    gemm_core4(g_Ctx + (size_t)m0 * IDIM, IDIM, g_Wo + (size_t)n0 * IDIM, IDIM,
               IDIM / BK, acc, dsm);
    EPI_VARS();
#pragma unroll
    for (int mi = 0; mi < 4; mi++)
#pragma unroll
        for (int ni = 0; ni < 4; ni++)
#pragma unroll
            for (int hh = 0; hh < 2; hh++) {
                int r = m0 + wm * 64 + mi * 16 + grp + hh * 8;
                int c = n0 + wn * 32 + ni * 8 + tid4 * 2;
                float g0 = 1.f / (1.f + ex2(-gate[c]     * L2E));
                float g1 = 1.f / (1.f + ex2(-gate[c + 1] * L2E));
                float v0 = (acc[mi][ni][hh * 2 + 0] + bo[c])     * g0;
                float v1 = (acc[mi][ni][hh * 2 + 1] + bo[c + 1]) * g1;
                float2 qv = *(const float2*)&query[(size_t)r * DDIM + c];
                float2 o; o.x = qv.x + v0; o.y = qv.y + v1;
                *(float2*)&out[(size_t)r * DDIM + c] = o;
            }
}

// ---------------- fused flash attention (2-stage pipelined, ldmatrix) --------
// Largest-first scheduling; exp2-domain softmax (MUFU.EX2); masked-tile fast
// path; warp-uniform O-rescale skip.
__global__ __launch_bounds__(256) void k_flash(const unsigned char* __restrict__ maskRaw)
{
    const int qt = (int)gridDim.x - 1 - (int)blockIdx.x;   // big CTAs first
    const int bh = blockIdx.y;
    const int b = bh >> 4, h = bh & 15;

    extern __shared__ bf16 sm[];
    __shared__ unsigned char mk[2][128];

    const int t = threadIdx.x, lane = t & 31, w = t >> 5;
    const int grp = lane >> 2, tid4 = lane & 3;
    const int useByte = g_maskByte;

    const int kRow = (lane & 7) + ((lane >> 4) << 3);
    const int kCol = (((lane >> 3) & 1) << 3);
    const int vRow = (lane & 15);
    const int vCol = ((lane >> 4) << 3);

    // scores scaled by C = 1/sqrt(128) * log2(e); all exponentials are exp2.
    const float C = 0.088388347648318447f * 1.4426950408889634f;

    // --- stage Q tile through stage-0 area, extract persistent A-fragments ---
    {
        bf16* SQ = sm;
        const bf16* Qg = g_Q + ((size_t)(b * TQS + qt * 128)) * IDIM + h * HDIM;
#pragma unroll
        for (int i = 0; i < 8; i++) {
            int idx = t + i * 256;
            int r = idx >> 4;
            int c = (idx & 15) * 8;
            *(float4*)(SQ + r * FST + c) = *(const float4*)(Qg + (size_t)r * IDIM + c);
        }
    }
    __syncthreads();
    uint32_t qf[8][4];
    {
        const bf16* SQ = sm;
        const int row = w * 16 + (lane & 15);
#pragma unroll
        for (int kc = 0; kc < 8; kc++)
            ldsm_x4(qf[kc], s2u(SQ + row * FST + kc * 16 + ((lane >> 4) << 3)));
    }
    __syncthreads();

    const bf16* Kb = g_K + ((size_t)(b * TKS)) * IDIM + h * HDIM;
    const bf16* Vb = g_V + ((size_t)(b * TKS)) * IDIM + h * HDIM;

    auto prefetch = [&](int kt, int s) {
        bf16* SK = sm + (size_t)s * (2 * 128 * FST);
        bf16* SV = SK + 128 * FST;
        const bf16* Kg = Kb + (size_t)(kt * 128) * IDIM;
        const bf16* Vg = Vb + (size_t)(kt * 128) * IDIM;
#pragma unroll
        for (int i = 0; i < 8; i++) {
            int idx = t + i * 256;
            int r = idx >> 4;
            int c = (idx & 15) * 8;
            cpa16(&SK[r * FST + c], Kg + (size_t)r * IDIM + c);
            cpa16(&SV[r * FST + c], Vg + (size_t)r * IDIM + c);
        }
        if (t < 128) {
            int k = kt * 128 + t;
            int mv = useByte ? (int)maskRaw[(size_t)b * TKS + k]
                             : ((const int*)maskRaw)[(size_t)b * TKS + k];
            mk[s][t] = (unsigned char)(mv != 0);
        }
        CP_COMMIT();
    };

    float m0 = -INFINITY, m1 = -INFINITY, l0 = 0.f, l1 = 0.f;
    float ao[16][4];
#pragma unroll
    for (int ni = 0; ni < 16; ni++)
#pragma unroll
        for (int j = 0; j < 4; j++) ao[ni][j] = 0.f;

    const int q0 = qt * 128 + w * 16 + grp;
    const int q1 = q0 + 8;

    prefetch(0, 0);
    int buf = 0;

    for (int kt = 0; kt <= qt; kt++) {
        if (kt < qt) {
            prefetch(kt + 1, buf ^ 1);
            CP_WAIT(1);
        } else {
            CP_WAIT(0);
        }
        __syncthreads();

        const bf16* SK = sm + (size_t)buf * (2 * 128 * FST);
        const bf16* SV = SK + 128 * FST;

        // --- S = Q K^T (16x128 per warp) ---
        float as_[16][4];
#pragma unroll
        for (int ni = 0; ni < 16; ni++)
#pragma unroll
            for (int j = 0; j < 4; j++) as_[ni][j] = 0.f;
#pragma unroll
        for (int kc = 0; kc < 8; kc++) {
#pragma unroll
            for (int ni = 0; ni < 16; ni += 2) {
                uint32_t bq[4];
                int n = ni * 8 + kRow;
                ldsm_x4(bq, s2u(SK + n * FST + kc * 16 + kCol));
                mma16816(as_[ni],     qf[kc], bq);
                mma16816(as_[ni + 1], qf[kc], bq + 2);
            }
        }

        // --- tile classification: clean (no causal, no padding) vs heavy ---
        bool heavy = (kt == qt);
        {
            uint32_t m4 = ((const uint32_t*)mk[buf])[lane];
            if (__ballot_sync(0xffffffffu, m4 != 0)) heavy = true;
        }

        // --- scale (+ masks on heavy path); row max (exp2 domain) ---
        float tm0 = -INFINITY, tm1 = -INFINITY;
        if (!heavy) {
#pragma unroll
            for (int ni = 0; ni < 16; ni++) {
                float s0 = as_[ni][0] * C;
                float s1 = as_[ni][1] * C;
                float s2 = as_[ni][2] * C;
                float s3 = as_[ni][3] * C;
                as_[ni][0] = s0; as_[ni][1] = s1; as_[ni][2] = s2; as_[ni][3] = s3;
                tm0 = fmaxf(tm0, fmaxf(s0, s1));
                tm1 = fmaxf(tm1, fmaxf(s2, s3));
            }
        } else {
#pragma unroll
            for (int ni = 0; ni < 16; ni++) {
                int kc0 = ni * 8 + tid4 * 2;
                int kg = kt * 128 + kc0;
                bool pm0 = mk[buf][kc0] != 0, pm1 = mk[buf][kc0 + 1] != 0;
                float s0 = (kg     > q0 || pm0) ? -INFINITY : as_[ni][0] * C;
                float s1 = (kg + 1 > q0 || pm1) ? -INFINITY : as_[ni][1] * C;
                float s2 = (kg     > q1 || pm0) ? -INFINITY : as_[ni][2] * C;
                float s3 = (kg + 1 > q1 || pm1) ? -INFINITY : as_[ni][3] * C;
                as_[ni][0] = s0; as_[ni][1] = s1; as_[ni][2] = s2; as_[ni][3] = s3;
                tm0 = fmaxf(tm0, fmaxf(s0, s1));
                tm1 = fmaxf(tm1, fmaxf(s2, s3));
            }
        }
        tm0 = fmaxf(tm0, __shfl_xor_sync(0xffffffffu, tm0, 1));
        tm0 = fmaxf(tm0, __shfl_xor_sync(0xffffffffu, tm0, 2));
        tm1 = fmaxf(tm1, __shfl_xor_sync(0xffffffffu, tm1, 1));
        tm1 = fmaxf(tm1, __shfl_xor_sync(0xffffffffu, tm1, 2));

        // --- online softmax update (exp2 domain, MUFU.EX2) ---
        const bool need = (tm0 > m0) || (tm1 > m1);
        const uint32_t vote = __ballot_sync(0xffffffffu, need);
        float mn0 = fmaxf(m0, tm0), mn1 = fmaxf(m1, tm1);

        float rs0, rs1;
        if (vote) {
            float f0 = ex2(m0 - mn0), f1 = ex2(m1 - mn1);
            m0 = mn0; m1 = mn1;
            rs0 = 0.f; rs1 = 0.f;
#pragma unroll
            for (int ni = 0; ni < 16; ni++) {
                float p0 = ex2(as_[ni][0] - mn0);
                float p1 = ex2(as_[ni][1] - mn0);
                float p2 = ex2(as_[ni][2] - mn1);
                float p3 = ex2(as_[ni][3] - mn1);
                as_[ni][0] = p0; as_[ni][1] = p1; as_[ni][2] = p2; as_[ni][3] = p3;
                rs0 += p0 + p1;
                rs1 += p2 + p3;
            }
            // rescale O accumulator
#pragma unroll
            for (int ni = 0; ni < 16; ni++) {
                ao[ni][0] *= f0; ao[ni][1] *= f0;
                ao[ni][2] *= f1; ao[ni][3] *= f1;
            }
            rs0 += __shfl_xor_sync(0xffffffffu, rs0, 1);
            rs0 += __shfl_xor_sync(0xffffffffu, rs0, 2);
            rs1 += __shfl_xor_sync(0xffffffffu, rs1, 1);
            rs1 += __shfl_xor_sync(0xffffffffu, rs1, 2);
            l0 = l0 * f0 + rs0;
            l1 = l1 * f1 + rs1;
        } else {
            // max unchanged for every row in this warp: f == 1 exactly
            rs0 = 0.f; rs1 = 0.f;
#pragma unroll
            for (int ni = 0; ni < 16; ni++) {
                float p0 = ex2(as_[ni][0] - mn0);
                float p1 = ex2(as_[ni][1] - mn0);
                float p2 = ex2(as_[ni][2] - mn1);
                float p3 = ex2(as_[ni][3] - mn1);
                as_[ni][0] = p0; as_[ni][1] = p1; as_[ni][2] = p2; as_[ni][3] = p3;
                rs0 += p0 + p1;
                rs1 += p2 + p3;
            }
            rs0 += __shfl_xor_sync(0xffffffffu, rs0, 1);
            rs0 += __shfl_xor_sync(0xffffffffu, rs0, 2);
            rs1 += __shfl_xor_sync(0xffffffffu, rs1, 1);
            rs1 += __shfl_xor_sync(0xffffffffu, rs1, 2);
            l0 += rs0;
            l1 += rs1;
        }

        // --- O += P V (P in regs; V via ldmatrix.trans) ---
#pragma unroll
        for (int kc = 0; kc < 8; kc++) {
            uint32_t pf[4];
            __nv_bfloat162 h0 = __float22bfloat162_rn(make_float2(as_[2*kc][0],   as_[2*kc][1]));
            __nv_bfloat162 h1 = __float22bfloat162_rn(make_float2(as_[2*kc][2],   as_[2*kc][3]));
            __nv_bfloat162 h2 = __float22bfloat162_rn(make_float2(as_[2*kc+1][0], as_[2*kc+1][1]));
            __nv_bfloat162 h3 = __float22bfloat162_rn(make_float2(as_[2*kc+1][2], as_[2*kc+1][3]));
            pf[0] = *(uint32_t*)&h0;
            pf[1] = *(uint32_t*)&h1;
            pf[2] = *(uint32_t*)&h2;
            pf[3] = *(uint32_t*)&h3;
#pragma unroll
            for (int ni = 0; ni < 16; ni += 2) {
                uint32_t bq[4];
                int row = kc * 16 + vRow;
                ldsm_x4_t(bq, s2u(SV + row * FST + ni * 8 + vCol));
                mma16816(ao[ni],     pf, bq);
                mma16816(ao[ni + 1], pf, bq + 2);
            }
        }
        __syncthreads();
        buf ^= 1;
    }

    // --- normalize and write ctx (bf16) ---
    const float inv0 = 1.f / l0, inv1 = 1.f / l1;
    bf16* Cg = g_Ctx + ((size_t)(b * TQS + qt * 128 + w * 16)) * IDIM + h * HDIM;
#pragma unroll
    for (int ni = 0; ni < 16; ni++) {
        int c = ni * 8 + tid4 * 2;
        __nv_bfloat162 o0 = __float22bfloat162_rn(make_float2(ao[ni][0] * inv0, ao[ni][1] * inv0));
        __nv_bfloat162 o1 = __float22bfloat162_rn(make_float2(ao[ni][2] * inv1, ao[ni][3] * inv1));
        *(__nv_bfloat162*)(Cg + (size_t)grp * IDIM + c)       = o0;
        *(__nv_bfloat162*)(Cg + (size_t)(grp + 8) * IDIM + c) = o1;
    }
}

// fused fp32 -> bf16 conversion over all 6 arrays; 2048 floats per block
struct CvtArgs {
    const float* src[6];
    bf16* dst[6];
    int end[6];   // cumulative block ends
};
__global__ __launch_bounds__(256) void k_cvt_all(CvtArgs a)
{
    int blk = blockIdx.x;
    int seg = 0;
#pragma unroll
    for (int s = 0; s < 5; s++) seg += (blk >= a.end[s]) ? 1 : 0;
    int base = seg ? a.end[seg - 1] : 0;
    int i0 = (blk - base) * 2048 + threadIdx.x * 4;
#pragma unroll
    for (int rep = 0; rep < 2; rep++) {
        int i = i0 + rep * 1024;
        float4 v = *(const float4*)(a.src[seg] + i);
        __nv_bfloat162 x, y;
        x.x = __float2bfloat16(v.x); x.y = __float2bfloat16(v.y);
        y.x = __float2bfloat16(v.z); y.y = __float2bfloat16(v.w);
        *(__nv_bfloat162*)(a.dst[seg] + i)     = x;
        *(__nv_bfloat162*)(a.dst[seg] + i + 2) = y;
    }
}

// detect mask storage layout: byte 4095 == 1 => 1-byte bool; == 0 => int32
__global__ void k_detect(const unsigned char* __restrict__ mask)
{
    g_maskByte = (mask[(size_t)NBATCH * TKS - 1] != 0) ? 1 : 0;
}

// ---------------- launch -----------------------------------------------------
extern "C" void kernel_launch(void* const* d_in, const int* in_sizes, int n_in,
                              void* d_out, int out_size)
{
    const float* query = (const float*)d_in[0];
    const float* kv    = (const float*)d_in[1];
    const unsigned char* mask = (const unsigned char*)d_in[2];
    const float* Wq = (const float*)d_in[3];
    const float* bq = (const float*)d_in[4];
    const float* Wk = (const float*)d_in[5];
    const float* bk = (const float*)d_in[6];
    const float* Wv = (const float*)d_in[7];
    const float* bv = (const float*)d_in[8];
    const float* Wo = (const float*)d_in[9];
    const float* bo = (const float*)d_in[10];
    const float* gate = (const float*)d_in[11];
    float* out = (float*)d_out;

    // symbol addresses
    bf16 *pXq, *pXkv, *pWq, *pWk, *pWv, *pWo, *pQ, *pK, *pV;
    cudaGetSymbolAddress((void**)&pXq,  g_Xq);
    cudaGetSymbolAddress((void**)&pXkv, g_Xkv);
    cudaGetSymbolAddress((void**)&pWq,  g_Wq);
    cudaGetSymbolAddress((void**)&pWk,  g_Wk);
    cudaGetSymbolAddress((void**)&pWv,  g_Wv);
    cudaGetSymbolAddress((void**)&pWo,  g_Wo);
    cudaGetSymbolAddress((void**)&pQ,   g_Q);
    cudaGetSymbolAddress((void**)&pK,   g_K);
    cudaGetSymbolAddress((void**)&pV,   g_V);

    static int attrSet = 0;
    const int FLASH_SMEM = 2 * 2 * 128 * FST * (int)sizeof(bf16);  // 139264
    if (!attrSet) {
        cudaFuncSetAttribute(k_flash, cudaFuncAttributeMaxDynamicSharedMemorySize, FLASH_SMEM);
        cudaFuncSetAttribute(k_qkv,   cudaFuncAttributeMaxDynamicSharedMemorySize, GEMM_SMEM);
        cudaFuncSetAttribute(k_out,   cudaFuncAttributeMaxDynamicSharedMemorySize, GEMM_SMEM);
        attrSet = 1;
    }

    k_detect<<<1, 1>>>(mask);

    // fused conversions: tokens (2 x 8.4M) + weights (4 x 4.2M)
    {
        CvtArgs a;
        a.src[0] = query; a.dst[0] = pXq;
        a.src[1] = kv;    a.dst[1] = pXkv;
        a.src[2] = Wq;    a.dst[2] = pWq;
        a.src[3] = Wk;    a.dst[3] = pWk;
        a.src[4] = Wv;    a.dst[4] = pWv;
        a.src[5] = Wo;    a.dst[5] = pWo;
        const int nTokB = NBATCH * TQS * DDIM / 2048;  // 4096 blocks
        const int nWB   = IDIM * DDIM / 2048;          // 2048 blocks
        int e = 0;
        e += nTokB; a.end[0] = e;
        e += nTokB; a.end[1] = e;
        e += nWB;   a.end[2] = e;
        e += nWB;   a.end[3] = e;
        e += nWB;   a.end[4] = e;
        e += nWB;   a.end[5] = e;
        k_cvt_all<<<e, 256>>>(a);
    }

    // fused Q/K/V projections: one launch, z in {0,1,2}
    {
        QkvArgs qa;
        qa.X[0] = pXq;  qa.W[0] = pWq; qa.bias[0] = bq; qa.out[0] = pQ;
        qa.X[1] = pXkv; qa.W[1] = pWk; qa.bias[1] = bk; qa.out[1] = pK;
        qa.X[2] = pXkv; qa.W[2] = pWv; qa.bias[2] = bv; qa.out[2] = pV;
        dim3 g(IDIM / BN, NBATCH * TQS / BM, 3);       // (16, 32, 3)
        k_qkv<<<g, 256, GEMM_SMEM>>>(qa);
    }

    k_flash<<<dim3(TQS / 128, NBH), 256, FLASH_SMEM>>>(mask);

    k_out<<<dim3(DDIM / BN, NBATCH * TQS / BM), 256, GEMM_SMEM>>>(query, bo, gate, out);
}